// round 10
// baseline (speedup 1.0000x reference)
#include <cuda_runtime.h>
#include <cuda_bf16.h>
#include <math.h>
#include <stdint.h>

#define NN  2048
#define TT  64
#define EE  16384
#define BB  64
#define C0  32
#define EMB 128
#define C1  64
#define C2  64
#define EPSB 1e-5f

// ---------------- scratch (device globals; BSS -> zero at load) ----------------
__device__ __nv_bfloat16 d_h1b[NN*TT*C0];    // conv1 out (8MB)
__device__ __nv_bfloat16 d_a1b[NN*TT*C0];    // agg1 out  (8MB)
__device__ __nv_bfloat16 d_h2b[NN*TT*EMB];   // gcn1/gcn2 out (32MB)
__device__ __nv_bfloat16 d_a2b[NN*TT*EMB];   // agg2 out  (32MB)
__device__ float d_gp[BB*14*C1];             // INVARIANT: zero at entry (k_final re-zeros)
__device__ int   d_rowcnt[NN];               // INVARIANT: zero at entry (prep last block re-zeros)
__device__ unsigned d_done;                  // INVARIANT: zero at entry (prep last block re-zeros)
__device__ int   d_rowstart[NN+1];
__device__ int   d_cursor[NN];
__device__ int   d_csrsrc[EE];
__device__ float d_dinv[NN];
__device__ __nv_bfloat16 d_w1tb[EMB*C0];       // gcn1 W transposed [n][k] bf16
__device__ __nv_bfloat16 d_w2tb[EMB*EMB];      // gcn2 W transposed [n][k] bf16
__device__ __nv_bfloat16 d_weff2tb[C1*1280];   // conv2 eff W transposed [c][u*128+ci] bf16
__device__ float d_beff2[C1];
__device__ float d_weff3[10*C2*C2];
__device__ float d_beff3[C2];

// ---------------- 1: prep (weight folds + degree count) + LAST-BLOCK scan ------------
__global__ void __launch_bounds__(256) k_prep(const int* __restrict__ edge,
                       const float* __restrict__ w1, const float* __restrict__ wg2,
                       const float* __restrict__ w2, const float* __restrict__ g2,
                       const float* __restrict__ b2, const float* __restrict__ m2,
                       const float* __restrict__ v2,
                       const float* __restrict__ w3, const float* __restrict__ g3,
                       const float* __restrict__ b3, const float* __restrict__ m3,
                       const float* __restrict__ v3) {
    __shared__ int sc[NN];       // per-chunk inclusive scans (last block only)
    __shared__ int st[256];
    __shared__ bool s_last;
    int tid = threadIdx.x;
    int i = blockIdx.x * blockDim.x + tid;
    if (i < EE) atomicAdd(&d_rowcnt[edge[EE + i]], 1);   // d_rowcnt zero by invariant
    if (i < C1) { float s = g2[i]*rsqrtf(v2[i]+EPSB); d_beff2[i]=b2[i]-m2[i]*s; }
    if (i < C2) { float s = g3[i]*rsqrtf(v3[i]+EPSB); d_beff3[i]=b3[i]-m3[i]*s; }
    if (i < EMB*C0) {
        int n = i >> 5, k = i & 31;
        d_w1tb[i] = __float2bfloat16(w1[k*EMB + n]);
    }
    if (i < EMB*EMB) {
        int n = i >> 7, k = i & 127;
        d_w2tb[i] = __float2bfloat16(wg2[k*EMB + n]);
    }
    if (i < C1*1280) {
        int c = i / 1280, kk = i - c*1280;
        int u = kk >> 7, ci = kk & 127;
        float s = g2[c]*rsqrtf(v2[c]+EPSB);
        int klo = u-3; if (klo < 0) klo = 0;
        int khi = u < 6 ? u : 6;
        float acc = 0.f;
        for (int k = klo; k <= khi; k++) acc += w2[(k*EMB+ci)*C1 + c];
        d_weff2tb[i] = __float2bfloat16(acc * s * 0.25f);
    }
    if (i < 10*C2*C2) {
        int c = i % C2; int ci = (i / C2) % C2; int u = i / (C2*C2);
        float s = g3[c]*rsqrtf(v3[c]+EPSB);
        int klo = u-3; if (klo < 0) klo = 0;
        int khi = u < 6 ? u : 6;
        float acc = 0.f;
        for (int k = klo; k <= khi; k++) acc += w3[(k*C2+ci)*C2 + c];
        d_weff3[i] = acc * s * 0.25f;
    }
    // ---- last-block-done: run the CSR scan once all degree atomics are visible ----
    __syncthreads();
    if (tid == 0) {
        __threadfence();
        unsigned t = atomicAdd(&d_done, 1u);
        s_last = (t == gridDim.x - 1);
    }
    __syncthreads();
    if (!s_last) return;

    // 256 threads scan 2048 counts: 8/thread chunk scan + block scan of partials
    int base = tid * 8;
    int run = 0;
    #pragma unroll
    for (int j = 0; j < 8; j++) {
        int c = d_rowcnt[base + j];
        d_rowcnt[base + j] = 0;                       // restore invariant
        d_dinv[base + j] = rsqrtf((float)(c + 1));
        run += c;
        sc[base + j] = run;                           // inclusive within chunk
    }
    st[tid] = run;
    __syncthreads();
    for (int off = 1; off < 256; off <<= 1) {
        int v = (tid >= off) ? st[tid - off] : 0;
        __syncthreads();
        st[tid] += v;
        __syncthreads();
    }
    int chunk_excl = (tid == 0) ? 0 : st[tid - 1];
    #pragma unroll
    for (int j = 0; j < 8; j++) {
        int excl = chunk_excl + ((j == 0) ? 0 : sc[base + j - 1]);
        d_rowstart[base + j] = excl;
        d_cursor[base + j]   = excl;
    }
    if (tid == 255) {
        d_rowstart[NN] = chunk_excl + sc[base + 7];   // total = EE
        d_done = 0;                                   // restore invariant
    }
}

// ---------------- 2: conv1(+inline bn1 fold) for blocks<NN; CSR scatter on the rest --
__global__ void __launch_bounds__(128) k_conv1sc(const float* __restrict__ x,
                                                const float* __restrict__ w,
                                                const float* __restrict__ g1,
                                                const float* __restrict__ b1,
                                                const float* __restrict__ m1,
                                                const float* __restrict__ v1,
                                                const int* __restrict__ edge) {
    int blk = blockIdx.x, tid = threadIdx.x;
    if (blk >= NN) {
        for (int e = (blk - NN)*128 + tid; e < EE; e += 32*128) {
            int dd = edge[EE + e];
            int pos = atomicAdd(&d_cursor[dd], 1);
            d_csrsrc[pos] = edge[e];
        }
        return;
    }
    __shared__ float xs[TT + 6];
    __shared__ float ws[7*C0];
    __shared__ float ss[C0], bs[C0];
    int n = blk;
    if (tid < TT) xs[tid + 3] = x[n*TT + tid];
    if (tid < 3)  { xs[tid] = 0.f; xs[TT + 3 + tid] = 0.f; }
    for (int i = tid; i < 7*C0; i += 128) ws[i] = w[i];
    if (tid < C0) {
        float s = g1[tid]*rsqrtf(v1[tid]+EPSB);
        ss[tid] = s; bs[tid] = b1[tid] - m1[tid]*s;
    }
    __syncthreads();
    int t = tid >> 1, cb = (tid & 1) * 16;
    float acc[16];
    #pragma unroll
    for (int c = 0; c < 16; c++) acc[c] = 0.f;
    #pragma unroll
    for (int k = 0; k < 7; k++) {
        float xv = xs[t + k];
        #pragma unroll
        for (int c = 0; c < 16; c++) acc[c] += xv * ws[k*C0 + cb + c];
    }
    uint4 o[2];
    __nv_bfloat162* ob = (__nv_bfloat162*)o;
    #pragma unroll
    for (int j = 0; j < 8; j++) {
        float f0 = fmaxf(acc[2*j]   * ss[cb+2*j]   + bs[cb+2*j],   0.f);
        float f1 = fmaxf(acc[2*j+1] * ss[cb+2*j+1] + bs[cb+2*j+1], 0.f);
        ob[j] = __floats2bfloat162_rn(f0, f1);
    }
    __nv_bfloat16* dst = &d_h1b[(n*TT + t)*C0 + cb];
    *(uint4*)dst = o[0];
    *(uint4*)(dst + 8) = o[1];
}

// ---------------- helpers ----------------
__device__ __forceinline__ void acc_u4(float* a, uint4 v, float w) {
    const __nv_bfloat162* b = (const __nv_bfloat162*)&v;
    #pragma unroll
    for (int j = 0; j < 4; j++) {
        float2 f = __bfloat1622float2(b[j]);
        a[2*j]   += w * f.x;
        a[2*j+1] += w * f.y;
    }
}
__device__ __forceinline__ void store_row8(__nv_bfloat16* p, const float* a, float sc) {
    uint4 o;
    __nv_bfloat162* b = (__nv_bfloat162*)&o;
    #pragma unroll
    for (int j = 0; j < 4; j++) b[j] = __floats2bfloat162_rn(a[2*j]*sc, a[2*j+1]*sc);
    *(uint4*)p = o;
}

// ---------------- 3: agg1 (bf16), 4-edge ILP gather ----------------
__global__ void __launch_bounds__(256) k_agg1b() {
    int node = blockIdx.x;
    int off  = threadIdx.x * 8;
    float di = d_dinv[node];
    float a[8] = {0,0,0,0,0,0,0,0};
    {
        uint4 v = *(const uint4*)(d_h1b + (size_t)node*2048 + off);
        acc_u4(a, v, di);
    }
    int e0 = d_rowstart[node], e1 = d_rowstart[node+1];
    int e = e0;
    for (; e + 4 <= e1; e += 4) {
        int s0 = d_csrsrc[e], s1 = d_csrsrc[e+1], s2 = d_csrsrc[e+2], s3 = d_csrsrc[e+3];
        float w0 = d_dinv[s0], w1 = d_dinv[s1], w2 = d_dinv[s2], w3 = d_dinv[s3];
        uint4 v0 = *(const uint4*)(d_h1b + (size_t)s0*2048 + off);
        uint4 v1 = *(const uint4*)(d_h1b + (size_t)s1*2048 + off);
        uint4 v2 = *(const uint4*)(d_h1b + (size_t)s2*2048 + off);
        uint4 v3 = *(const uint4*)(d_h1b + (size_t)s3*2048 + off);
        acc_u4(a, v0, w0); acc_u4(a, v1, w1); acc_u4(a, v2, w2); acc_u4(a, v3, w3);
    }
    for (; e < e1; e++) {
        int s = d_csrsrc[e];
        float w = d_dinv[s];
        uint4 v = *(const uint4*)(d_h1b + (size_t)s*2048 + off);
        acc_u4(a, v, w);
    }
    store_row8(d_a1b + (size_t)node*2048 + off, a, di);
}

// ---------------- 5: agg2 (bf16), grid.y=4, 4-edge ILP gather ----------------
__global__ void __launch_bounds__(256) k_agg2b() {
    int node = blockIdx.x;
    int off  = blockIdx.y*2048 + threadIdx.x * 8;
    float di = d_dinv[node];
    float a[8] = {0,0,0,0,0,0,0,0};
    {
        uint4 v = *(const uint4*)(d_h2b + (size_t)node*8192 + off);
        acc_u4(a, v, di);
    }
    int e0 = d_rowstart[node], e1 = d_rowstart[node+1];
    int e = e0;
    for (; e + 4 <= e1; e += 4) {
        int s0 = d_csrsrc[e], s1 = d_csrsrc[e+1], s2 = d_csrsrc[e+2], s3 = d_csrsrc[e+3];
        float w0 = d_dinv[s0], w1 = d_dinv[s1], w2 = d_dinv[s2], w3 = d_dinv[s3];
        uint4 v0 = *(const uint4*)(d_h2b + (size_t)s0*8192 + off);
        uint4 v1 = *(const uint4*)(d_h2b + (size_t)s1*8192 + off);
        uint4 v2 = *(const uint4*)(d_h2b + (size_t)s2*8192 + off);
        uint4 v3 = *(const uint4*)(d_h2b + (size_t)s3*8192 + off);
        acc_u4(a, v0, w0); acc_u4(a, v1, w1); acc_u4(a, v2, w2); acc_u4(a, v3, w3);
    }
    for (; e < e1; e++) {
        int s = d_csrsrc[e];
        float w = d_dinv[s];
        uint4 v = *(const uint4*)(d_h2b + (size_t)s*8192 + off);
        acc_u4(a, v, w);
    }
    store_row8(d_a2b + (size_t)node*8192 + off, a, di);
}

// ---------------- bf16 mma macro ----------------
#define MMA_BF16(acc, A0, A1, A2, A3, B0, B1)                                   \
    asm volatile(                                                               \
        "mma.sync.aligned.m16n8k16.row.col.f32.bf16.bf16.f32 "                  \
        "{%0,%1,%2,%3}, {%4,%5,%6,%7}, {%8,%9}, {%0,%1,%2,%3};"                 \
        : "+f"(acc[0]), "+f"(acc[1]), "+f"(acc[2]), "+f"(acc[3])                \
        : "r"(A0), "r"(A1), "r"(A2), "r"(A3), "r"(B0), "r"(B1))

// ---------------- 4: gcn1 matmul bf16 mma: (131072,32)@(32,128)+bias+relu -> bf16 -----
__global__ void __launch_bounds__(256) k_mm1b(const float* __restrict__ bias) {
    __shared__ __nv_bfloat16 As[128*40];
    __shared__ __nv_bfloat16 Bs[128*40];
    int tid = threadIdx.x;
    int wid = tid >> 5, lane = tid & 31;
    int g = lane >> 2, tg = lane & 3;
    int rowbase = blockIdx.x * 128;
    int mrow = wid * 16;

    float acc[16][4];
    #pragma unroll
    for (int nt = 0; nt < 16; nt++) {
        int c = nt*8 + 2*tg;
        float b0 = bias[c], b1 = bias[c+1];
        acc[nt][0] = b0; acc[nt][1] = b1; acc[nt][2] = b0; acc[nt][3] = b1;
    }
    #pragma unroll
    for (int i = tid; i < 512; i += 256) {
        int r = i >> 2, k8 = (i & 3) * 8;
        *(uint4*)&As[r*40 + k8] = *(const uint4*)&d_a1b[(size_t)(rowbase + r)*C0 + k8];
    }
    #pragma unroll
    for (int i = tid; i < 512; i += 256) {
        int r = i >> 2, k8 = (i & 3) * 8;
        *(uint4*)&Bs[r*40 + k8] = *(const uint4*)&d_w1tb[r*C0 + k8];
    }
    __syncthreads();
    #pragma unroll
    for (int ks = 0; ks < 32; ks += 16) {
        uint32_t a0 = *(const uint32_t*)&As[(mrow+g  )*40 + ks + 2*tg];
        uint32_t a1 = *(const uint32_t*)&As[(mrow+g+8)*40 + ks + 2*tg];
        uint32_t a2 = *(const uint32_t*)&As[(mrow+g  )*40 + ks + 2*tg + 8];
        uint32_t a3 = *(const uint32_t*)&As[(mrow+g+8)*40 + ks + 2*tg + 8];
        #pragma unroll
        for (int nt = 0; nt < 16; nt++) {
            uint32_t b0 = *(const uint32_t*)&Bs[(nt*8+g)*40 + ks + 2*tg];
            uint32_t b1 = *(const uint32_t*)&Bs[(nt*8+g)*40 + ks + 2*tg + 8];
            MMA_BF16(acc[nt], a0, a1, a2, a3, b0, b1);
        }
    }
    int row0 = rowbase + mrow + g;
    int row1 = row0 + 8;
    #pragma unroll
    for (int nt = 0; nt < 16; nt++) {
        int c = nt*8 + 2*tg;
        *(__nv_bfloat162*)&d_h2b[(size_t)row0*EMB + c] =
            __floats2bfloat162_rn(fmaxf(acc[nt][0], 0.f), fmaxf(acc[nt][1], 0.f));
        *(__nv_bfloat162*)&d_h2b[(size_t)row1*EMB + c] =
            __floats2bfloat162_rn(fmaxf(acc[nt][2], 0.f), fmaxf(acc[nt][3], 0.f));
    }
}

// ---------------- 6: gcn2 matmul bf16 mma: (131072,128)@(128,128)+bias+relu -> bf16 ---
__global__ void __launch_bounds__(256) k_mm2b(const float* __restrict__ bias) {
    __shared__ __nv_bfloat16 As[128*40];
    __shared__ __nv_bfloat16 Bs[128*40];
    int tid = threadIdx.x;
    int wid = tid >> 5, lane = tid & 31;
    int g = lane >> 2, tg = lane & 3;
    int rowbase = blockIdx.x * 128;
    int mrow = wid * 16;

    float acc[16][4];
    #pragma unroll
    for (int nt = 0; nt < 16; nt++) {
        int c = nt*8 + 2*tg;
        float b0 = bias[c], b1 = bias[c+1];
        acc[nt][0] = b0; acc[nt][1] = b1; acc[nt][2] = b0; acc[nt][3] = b1;
    }
    for (int kc = 0; kc < 4; kc++) {
        #pragma unroll
        for (int i = tid; i < 512; i += 256) {
            int r = i >> 2, k8 = (i & 3) * 8;
            *(uint4*)&As[r*40 + k8] =
                *(const uint4*)&d_a2b[(size_t)(rowbase + r)*EMB + kc*32 + k8];
        }
        #pragma unroll
        for (int i = tid; i < 512; i += 256) {
            int r = i >> 2, k8 = (i & 3) * 8;
            *(uint4*)&Bs[r*40 + k8] = *(const uint4*)&d_w2tb[r*EMB + kc*32 + k8];
        }
        __syncthreads();
        #pragma unroll
        for (int ks = 0; ks < 32; ks += 16) {
            uint32_t a0 = *(const uint32_t*)&As[(mrow+g  )*40 + ks + 2*tg];
            uint32_t a1 = *(const uint32_t*)&As[(mrow+g+8)*40 + ks + 2*tg];
            uint32_t a2 = *(const uint32_t*)&As[(mrow+g  )*40 + ks + 2*tg + 8];
            uint32_t a3 = *(const uint32_t*)&As[(mrow+g+8)*40 + ks + 2*tg + 8];
            #pragma unroll
            for (int nt = 0; nt < 16; nt++) {
                uint32_t b0 = *(const uint32_t*)&Bs[(nt*8+g)*40 + ks + 2*tg];
                uint32_t b1 = *(const uint32_t*)&Bs[(nt*8+g)*40 + ks + 2*tg + 8];
                MMA_BF16(acc[nt], a0, a1, a2, a3, b0, b1);
            }
        }
        __syncthreads();
    }
    int row0 = rowbase + mrow + g;
    int row1 = row0 + 8;
    #pragma unroll
    for (int nt = 0; nt < 16; nt++) {
        int c = nt*8 + 2*tg;
        *(__nv_bfloat162*)&d_h2b[(size_t)row0*EMB + c] =
            __floats2bfloat162_rn(fmaxf(acc[nt][0], 0.f), fmaxf(acc[nt][1], 0.f));
        *(__nv_bfloat162*)&d_h2b[(size_t)row1*EMB + c] =
            __floats2bfloat162_rn(fmaxf(acc[nt][2], 0.f), fmaxf(acc[nt][3], 0.f));
    }
}

// ---------------- 7: conv2+bn2+pool+relu GEMM, fused graph-pool epilogue --------------
__global__ void __launch_bounds__(256) k_conv2b(const int* __restrict__ batch) {
    __shared__ __nv_bfloat16 As[128*72];   // 18KB
    __shared__ __nv_bfloat16 Bs[64*72];    // 9KB
    int tid = threadIdx.x;
    int wid = tid >> 5, lane = tid & 31;
    int g = lane >> 2, tg = lane & 3;
    int n0 = blockIdx.x * 8;
    int mrow = wid * 16;

    float acc[8][4];
    #pragma unroll
    for (int nt = 0; nt < 8; nt++) {
        int c = nt*8 + 2*tg;
        float b0 = d_beff2[c], b1 = d_beff2[c+1];
        acc[nt][0] = b0; acc[nt][1] = b1; acc[nt][2] = b0; acc[nt][3] = b1;
    }
    for (int u = 0; u < 10; u++) {
        for (int h = 0; h < 2; h++) {
            #pragma unroll
            for (int i = tid; i < 1024; i += 256) {
                int r = i >> 3, k8 = (i & 7) * 8;
                uint4 v = make_uint4(0u, 0u, 0u, 0u);
                if (r < 112) {
                    int nl = r / 14, p = r - nl*14;
                    v = *(const uint4*)
                        &d_h2b[(size_t)((n0+nl)*TT + 4*p + u)*EMB + h*64 + k8];
                }
                *(uint4*)&As[r*72 + k8] = v;
            }
            #pragma unroll
            for (int i = tid; i < 512; i += 256) {
                int c = i >> 3, k8 = (i & 7) * 8;
                *(uint4*)&Bs[c*72 + k8] =
                    *(const uint4*)&d_weff2tb[(size_t)c*1280 + u*128 + h*64 + k8];
            }
            __syncthreads();
            #pragma unroll
            for (int ks = 0; ks < 64; ks += 16) {
                uint32_t a0 = *(const uint32_t*)&As[(mrow+g  )*72 + ks + 2*tg];
                uint32_t a1 = *(const uint32_t*)&As[(mrow+g+8)*72 + ks + 2*tg];
                uint32_t a2 = *(const uint32_t*)&As[(mrow+g  )*72 + ks + 2*tg + 8];
                uint32_t a3 = *(const uint32_t*)&As[(mrow+g+8)*72 + ks + 2*tg + 8];
                #pragma unroll
                for (int nt = 0; nt < 8; nt++) {
                    uint32_t b0 = *(const uint32_t*)&Bs[(nt*8+g)*72 + ks + 2*tg];
                    uint32_t b1 = *(const uint32_t*)&Bs[(nt*8+g)*72 + ks + 2*tg + 8];
                    MMA_BF16(acc[nt], a0, a1, a2, a3, b0, b1);
                }
            }
            __syncthreads();
        }
    }
    int r0 = mrow + g;
    if (r0 < 112) {
        int nl0 = r0 / 14, p0 = r0 - nl0*14;
        int base0 = batch[n0 + nl0]*(14*C1) + p0*C1;
        int r1 = r0 + 8;
        int nl1 = r1 / 14, p1 = r1 - nl1*14;
        int base1 = batch[n0 + nl1]*(14*C1) + p1*C1;
        #pragma unroll
        for (int nt = 0; nt < 8; nt++) {
            int c = nt*8 + 2*tg;
            atomicAdd(&d_gp[base0 + c],     fmaxf(acc[nt][0], 0.f));
            atomicAdd(&d_gp[base0 + c + 1], fmaxf(acc[nt][1], 0.f));
            atomicAdd(&d_gp[base1 + c],     fmaxf(acc[nt][2], 0.f));
            atomicAdd(&d_gp[base1 + c + 1], fmaxf(acc[nt][3], 0.f));
        }
    }
}

// ---------------- 8: conv3+bn3+pool+relu + dense + log_softmax (+restore d_gp zero) ---
__global__ void __launch_bounds__(128) k_final(const int* __restrict__ batch,
                                               const float* __restrict__ dw,
                                               const float* __restrict__ db,
                                               float* __restrict__ out) {
    __shared__ float gin[14*C1];
    __shared__ float flat[128];
    __shared__ float lg[4];
    __shared__ int scount;
    int b = blockIdx.x, tid = threadIdx.x;
    if (tid == 0) scount = 0;
    __syncthreads();
    int cnt = 0;
    for (int i = tid; i < NN; i += 128) cnt += (batch[i] == b);
    #pragma unroll
    for (int s = 16; s > 0; s >>= 1) cnt += __shfl_down_sync(0xffffffffu, cnt, s);
    if ((tid & 31) == 0) atomicAdd(&scount, cnt);
    for (int i = tid; i < 14*C1; i += 128) gin[i] = d_gp[b*14*C1 + i];
    __syncthreads();
    float inv = 1.f / (float)scount;
    for (int i = tid; i < 14*C1; i += 128) d_gp[b*14*C1 + i] = 0.f;
    int p = tid >> 6, c = tid & 63;
    float acc = d_beff3[c];
    for (int u = 0; u < 10; u++)
        for (int ci = 0; ci < C2; ci++)
            acc += gin[(4*p + u)*C2 + ci] * inv * d_weff3[(u*C2 + ci)*C2 + c];
    flat[p*64 + c] = fmaxf(acc, 0.f);
    __syncthreads();
    if (tid < 4) {
        float a = db[tid];
        for (int i = 0; i < 128; i++) a += flat[i] * dw[i*4 + tid];
        lg[tid] = a;
    }
    __syncthreads();
    if (tid == 0) {
        float m = fmaxf(fmaxf(lg[0], lg[1]), fmaxf(lg[2], lg[3]));
        float se = expf(lg[0]-m) + expf(lg[1]-m) + expf(lg[2]-m) + expf(lg[3]-m);
        float lse = logf(se) + m;
        for (int j = 0; j < 4; j++) out[b*4 + j] = lg[j] - lse;
    }
}

// ---------------- launcher ----------------
extern "C" void kernel_launch(void* const* d_in, const int* in_sizes, int n_in,
                              void* d_out, int out_size) {
    const float* x       = (const float*)d_in[0];
    const int*   edge    = (const int*)d_in[1];
    const int*   batch   = (const int*)d_in[2];
    const float* conv1_w = (const float*)d_in[3];
    const float* bn1_g   = (const float*)d_in[4];
    const float* bn1_b   = (const float*)d_in[5];
    const float* bn1_m   = (const float*)d_in[6];
    const float* bn1_v   = (const float*)d_in[7];
    const float* gcn1_w  = (const float*)d_in[8];
    const float* gcn1_b  = (const float*)d_in[9];
    const float* gcn2_w  = (const float*)d_in[10];
    const float* gcn2_b  = (const float*)d_in[11];
    const float* conv2_w = (const float*)d_in[12];
    const float* bn2_g   = (const float*)d_in[13];
    const float* bn2_b   = (const float*)d_in[14];
    const float* bn2_m   = (const float*)d_in[15];
    const float* bn2_v   = (const float*)d_in[16];
    const float* conv3_w = (const float*)d_in[17];
    const float* bn3_g   = (const float*)d_in[18];
    const float* bn3_b   = (const float*)d_in[19];
    const float* bn3_m   = (const float*)d_in[20];
    const float* bn3_v   = (const float*)d_in[21];
    const float* dense_w = (const float*)d_in[22];
    const float* dense_b = (const float*)d_in[23];
    float* out = (float*)d_out;

    k_prep<<<320, 256>>>(edge, gcn1_w, gcn2_w,
                         conv2_w, bn2_g, bn2_b, bn2_m, bn2_v,
                         conv3_w, bn3_g, bn3_b, bn3_m, bn3_v);
    k_conv1sc<<<NN + 32, 128>>>(x, conv1_w, bn1_g, bn1_b, bn1_m, bn1_v, edge);
    k_agg1b<<<NN, 256>>>();
    k_mm1b<<<1024, 256>>>(gcn1_b);
    k_agg2b<<<dim3(NN, 4), 256>>>();
    k_mm2b<<<1024, 256>>>(gcn2_b);
    k_conv2b<<<256, 256>>>(batch);
    k_final<<<BB, 128>>>(batch, dense_w, dense_b, out);
}

// round 11
// speedup vs baseline: 1.0135x; 1.0135x over previous
#include <cuda_runtime.h>
#include <cuda_bf16.h>
#include <math.h>
#include <stdint.h>

#define NN  2048
#define TT  64
#define EE  16384
#define BB  64
#define C0  32
#define EMB 128
#define C1  64
#define C2  64
#define EPSB 1e-5f

// ---------------- scratch (device globals; BSS -> zero at load) ----------------
__device__ __nv_bfloat16 d_h1b[NN*TT*C0];    // conv1 out (8MB)
__device__ __nv_bfloat16 d_a1b[NN*TT*C0];    // agg1 out  (8MB)
__device__ __nv_bfloat16 d_h2b[NN*TT*EMB];   // gcn1/gcn2 out (32MB)
__device__ __nv_bfloat16 d_a2b[NN*TT*EMB];   // agg2 out  (32MB)
__device__ float d_gp[BB*14*C1];             // INVARIANT: zero at entry (k_final re-zeros)
__device__ int   d_rowcnt[NN];               // INVARIANT: zero at entry (prep last block re-zeros)
__device__ unsigned d_done;                  // INVARIANT: zero at entry (prep last block re-zeros)
__device__ int   d_rowstart[NN+1];
__device__ int   d_cursor[NN];
__device__ int   d_csrsrc[EE];
__device__ float d_dinv[NN];
__device__ __nv_bfloat16 d_w1tb[EMB*C0];       // gcn1 W transposed [n][k] bf16
__device__ __nv_bfloat16 d_w2tb[EMB*EMB];      // gcn2 W transposed [n][k] bf16
__device__ __nv_bfloat16 d_weff2tb[C1*1280];   // conv2 eff W transposed [c][u*128+ci] bf16
__device__ float d_beff2[C1];
__device__ float d_weff3[10*C2*C2];
__device__ float d_beff3[C2];

// ---------------- 1: prep (weight folds + degree count) + LAST-BLOCK scan ------------
__global__ void __launch_bounds__(256) k_prep(const int* __restrict__ edge,
                       const float* __restrict__ w1, const float* __restrict__ wg2,
                       const float* __restrict__ w2, const float* __restrict__ g2,
                       const float* __restrict__ b2, const float* __restrict__ m2,
                       const float* __restrict__ v2,
                       const float* __restrict__ w3, const float* __restrict__ g3,
                       const float* __restrict__ b3, const float* __restrict__ m3,
                       const float* __restrict__ v3) {
    __shared__ int sc[NN];       // per-chunk inclusive scans (last block only)
    __shared__ int st[256];
    __shared__ bool s_last;
    int tid = threadIdx.x;
    int i = blockIdx.x * blockDim.x + tid;
    if (i < EE) atomicAdd(&d_rowcnt[edge[EE + i]], 1);   // d_rowcnt zero by invariant
    if (i < C1) { float s = g2[i]*rsqrtf(v2[i]+EPSB); d_beff2[i]=b2[i]-m2[i]*s; }
    if (i < C2) { float s = g3[i]*rsqrtf(v3[i]+EPSB); d_beff3[i]=b3[i]-m3[i]*s; }
    if (i < EMB*C0) {
        int n = i >> 5, k = i & 31;
        d_w1tb[i] = __float2bfloat16(w1[k*EMB + n]);
    }
    if (i < EMB*EMB) {
        int n = i >> 7, k = i & 127;
        d_w2tb[i] = __float2bfloat16(wg2[k*EMB + n]);
    }
    if (i < C1*1280) {
        int c = i / 1280, kk = i - c*1280;
        int u = kk >> 7, ci = kk & 127;
        float s = g2[c]*rsqrtf(v2[c]+EPSB);
        int klo = u-3; if (klo < 0) klo = 0;
        int khi = u < 6 ? u : 6;
        float acc = 0.f;
        for (int k = klo; k <= khi; k++) acc += w2[(k*EMB+ci)*C1 + c];
        d_weff2tb[i] = __float2bfloat16(acc * s * 0.25f);
    }
    if (i < 10*C2*C2) {
        int c = i % C2; int ci = (i / C2) % C2; int u = i / (C2*C2);
        float s = g3[c]*rsqrtf(v3[c]+EPSB);
        int klo = u-3; if (klo < 0) klo = 0;
        int khi = u < 6 ? u : 6;
        float acc = 0.f;
        for (int k = klo; k <= khi; k++) acc += w3[(k*C2+ci)*C2 + c];
        d_weff3[i] = acc * s * 0.25f;
    }
    // ---- last-block-done: run the CSR scan once all degree atomics are visible ----
    __syncthreads();
    if (tid == 0) {
        __threadfence();
        unsigned t = atomicAdd(&d_done, 1u);
        s_last = (t == gridDim.x - 1);
    }
    __syncthreads();
    if (!s_last) return;

    // 256 threads scan 2048 counts: 8/thread chunk scan + block scan of partials
    int base = tid * 8;
    int run = 0;
    #pragma unroll
    for (int j = 0; j < 8; j++) {
        int c = d_rowcnt[base + j];
        d_rowcnt[base + j] = 0;                       // restore invariant
        d_dinv[base + j] = rsqrtf((float)(c + 1));
        run += c;
        sc[base + j] = run;                           // inclusive within chunk
    }
    st[tid] = run;
    __syncthreads();
    for (int off = 1; off < 256; off <<= 1) {
        int v = (tid >= off) ? st[tid - off] : 0;
        __syncthreads();
        st[tid] += v;
        __syncthreads();
    }
    int chunk_excl = (tid == 0) ? 0 : st[tid - 1];
    #pragma unroll
    for (int j = 0; j < 8; j++) {
        int excl = chunk_excl + ((j == 0) ? 0 : sc[base + j - 1]);
        d_rowstart[base + j] = excl;
        d_cursor[base + j]   = excl;
    }
    if (tid == 255) {
        d_rowstart[NN] = chunk_excl + sc[base + 7];   // total = EE
        d_done = 0;                                   // restore invariant
    }
}

// ---------------- 2: conv1(+inline bn1 fold) for blocks<NN; CSR scatter on the rest --
__global__ void __launch_bounds__(128) k_conv1sc(const float* __restrict__ x,
                                                const float* __restrict__ w,
                                                const float* __restrict__ g1,
                                                const float* __restrict__ b1,
                                                const float* __restrict__ m1,
                                                const float* __restrict__ v1,
                                                const int* __restrict__ edge) {
    int blk = blockIdx.x, tid = threadIdx.x;
    if (blk >= NN) {
        for (int e = (blk - NN)*128 + tid; e < EE; e += 32*128) {
            int dd = edge[EE + e];
            int pos = atomicAdd(&d_cursor[dd], 1);
            d_csrsrc[pos] = edge[e];
        }
        return;
    }
    __shared__ float xs[TT + 6];
    __shared__ float ws[7*C0];
    __shared__ float ss[C0], bs[C0];
    int n = blk;
    if (tid < TT) xs[tid + 3] = x[n*TT + tid];
    if (tid < 3)  { xs[tid] = 0.f; xs[TT + 3 + tid] = 0.f; }
    for (int i = tid; i < 7*C0; i += 128) ws[i] = w[i];
    if (tid < C0) {
        float s = g1[tid]*rsqrtf(v1[tid]+EPSB);
        ss[tid] = s; bs[tid] = b1[tid] - m1[tid]*s;
    }
    __syncthreads();
    int t = tid >> 1, cb = (tid & 1) * 16;
    float acc[16];
    #pragma unroll
    for (int c = 0; c < 16; c++) acc[c] = 0.f;
    #pragma unroll
    for (int k = 0; k < 7; k++) {
        float xv = xs[t + k];
        #pragma unroll
        for (int c = 0; c < 16; c++) acc[c] += xv * ws[k*C0 + cb + c];
    }
    uint4 o[2];
    __nv_bfloat162* ob = (__nv_bfloat162*)o;
    #pragma unroll
    for (int j = 0; j < 8; j++) {
        float f0 = fmaxf(acc[2*j]   * ss[cb+2*j]   + bs[cb+2*j],   0.f);
        float f1 = fmaxf(acc[2*j+1] * ss[cb+2*j+1] + bs[cb+2*j+1], 0.f);
        ob[j] = __floats2bfloat162_rn(f0, f1);
    }
    __nv_bfloat16* dst = &d_h1b[(n*TT + t)*C0 + cb];
    *(uint4*)dst = o[0];
    *(uint4*)(dst + 8) = o[1];
}

// ---------------- helpers ----------------
__device__ __forceinline__ void acc_u4(float* a, uint4 v, float w) {
    const __nv_bfloat162* b = (const __nv_bfloat162*)&v;
    #pragma unroll
    for (int j = 0; j < 4; j++) {
        float2 f = __bfloat1622float2(b[j]);
        a[2*j]   += w * f.x;
        a[2*j+1] += w * f.y;
    }
}
__device__ __forceinline__ void store_row8(__nv_bfloat16* p, const float* a, float sc) {
    uint4 o;
    __nv_bfloat162* b = (__nv_bfloat162*)&o;
    #pragma unroll
    for (int j = 0; j < 4; j++) b[j] = __floats2bfloat162_rn(a[2*j]*sc, a[2*j+1]*sc);
    *(uint4*)p = o;
}

// ---------------- 3: agg1 (bf16), 4-edge ILP gather ----------------
__global__ void __launch_bounds__(256) k_agg1b() {
    int node = blockIdx.x;
    int off  = threadIdx.x * 8;
    float di = d_dinv[node];
    float a[8] = {0,0,0,0,0,0,0,0};
    {
        uint4 v = *(const uint4*)(d_h1b + (size_t)node*2048 + off);
        acc_u4(a, v, di);
    }
    int e0 = d_rowstart[node], e1 = d_rowstart[node+1];
    int e = e0;
    for (; e + 4 <= e1; e += 4) {
        int s0 = d_csrsrc[e], s1 = d_csrsrc[e+1], s2 = d_csrsrc[e+2], s3 = d_csrsrc[e+3];
        float w0 = d_dinv[s0], w1 = d_dinv[s1], w2 = d_dinv[s2], w3 = d_dinv[s3];
        uint4 v0 = *(const uint4*)(d_h1b + (size_t)s0*2048 + off);
        uint4 v1 = *(const uint4*)(d_h1b + (size_t)s1*2048 + off);
        uint4 v2 = *(const uint4*)(d_h1b + (size_t)s2*2048 + off);
        uint4 v3 = *(const uint4*)(d_h1b + (size_t)s3*2048 + off);
        acc_u4(a, v0, w0); acc_u4(a, v1, w1); acc_u4(a, v2, w2); acc_u4(a, v3, w3);
    }
    for (; e < e1; e++) {
        int s = d_csrsrc[e];
        float w = d_dinv[s];
        uint4 v = *(const uint4*)(d_h1b + (size_t)s*2048 + off);
        acc_u4(a, v, w);
    }
    store_row8(d_a1b + (size_t)node*2048 + off, a, di);
}

// ---------------- 5: agg2 (bf16), grid.y=4, 4-edge ILP gather ----------------
__global__ void __launch_bounds__(256) k_agg2b() {
    int node = blockIdx.x;
    int off  = blockIdx.y*2048 + threadIdx.x * 8;
    float di = d_dinv[node];
    float a[8] = {0,0,0,0,0,0,0,0};
    {
        uint4 v = *(const uint4*)(d_h2b + (size_t)node*8192 + off);
        acc_u4(a, v, di);
    }
    int e0 = d_rowstart[node], e1 = d_rowstart[node+1];
    int e = e0;
    for (; e + 4 <= e1; e += 4) {
        int s0 = d_csrsrc[e], s1 = d_csrsrc[e+1], s2 = d_csrsrc[e+2], s3 = d_csrsrc[e+3];
        float w0 = d_dinv[s0], w1 = d_dinv[s1], w2 = d_dinv[s2], w3 = d_dinv[s3];
        uint4 v0 = *(const uint4*)(d_h2b + (size_t)s0*8192 + off);
        uint4 v1 = *(const uint4*)(d_h2b + (size_t)s1*8192 + off);
        uint4 v2 = *(const uint4*)(d_h2b + (size_t)s2*8192 + off);
        uint4 v3 = *(const uint4*)(d_h2b + (size_t)s3*8192 + off);
        acc_u4(a, v0, w0); acc_u4(a, v1, w1); acc_u4(a, v2, w2); acc_u4(a, v3, w3);
    }
    for (; e < e1; e++) {
        int s = d_csrsrc[e];
        float w = d_dinv[s];
        uint4 v = *(const uint4*)(d_h2b + (size_t)s*8192 + off);
        acc_u4(a, v, w);
    }
    store_row8(d_a2b + (size_t)node*8192 + off, a, di);
}

// ---------------- bf16 mma macro ----------------
#define MMA_BF16(acc, A0, A1, A2, A3, B0, B1)                                   \
    asm volatile(                                                               \
        "mma.sync.aligned.m16n8k16.row.col.f32.bf16.bf16.f32 "                  \
        "{%0,%1,%2,%3}, {%4,%5,%6,%7}, {%8,%9}, {%0,%1,%2,%3};"                 \
        : "+f"(acc[0]), "+f"(acc[1]), "+f"(acc[2]), "+f"(acc[3])                \
        : "r"(A0), "r"(A1), "r"(A2), "r"(A3), "r"(B0), "r"(B1))

// ---------------- 4: gcn1 matmul bf16 mma (spill-free: 2 blocks/SM -> 128 reg budget) -
__global__ void __launch_bounds__(256, 2) k_mm1b(const float* __restrict__ bias) {
    __shared__ __nv_bfloat16 As[128*40];
    __shared__ __nv_bfloat16 Bs[128*40];
    int tid = threadIdx.x;
    int wid = tid >> 5, lane = tid & 31;
    int g = lane >> 2, tg = lane & 3;
    int rowbase = blockIdx.x * 128;
    int mrow = wid * 16;

    float acc[16][4];
    #pragma unroll
    for (int nt = 0; nt < 16; nt++) {
        int c = nt*8 + 2*tg;
        float b0 = bias[c], b1 = bias[c+1];
        acc[nt][0] = b0; acc[nt][1] = b1; acc[nt][2] = b0; acc[nt][3] = b1;
    }
    #pragma unroll
    for (int i = tid; i < 512; i += 256) {
        int r = i >> 2, k8 = (i & 3) * 8;
        *(uint4*)&As[r*40 + k8] = *(const uint4*)&d_a1b[(size_t)(rowbase + r)*C0 + k8];
    }
    #pragma unroll
    for (int i = tid; i < 512; i += 256) {
        int r = i >> 2, k8 = (i & 3) * 8;
        *(uint4*)&Bs[r*40 + k8] = *(const uint4*)&d_w1tb[r*C0 + k8];
    }
    __syncthreads();
    #pragma unroll
    for (int ks = 0; ks < 32; ks += 16) {
        uint32_t a0 = *(const uint32_t*)&As[(mrow+g  )*40 + ks + 2*tg];
        uint32_t a1 = *(const uint32_t*)&As[(mrow+g+8)*40 + ks + 2*tg];
        uint32_t a2 = *(const uint32_t*)&As[(mrow+g  )*40 + ks + 2*tg + 8];
        uint32_t a3 = *(const uint32_t*)&As[(mrow+g+8)*40 + ks + 2*tg + 8];
        #pragma unroll
        for (int nt = 0; nt < 16; nt++) {
            uint32_t b0 = *(const uint32_t*)&Bs[(nt*8+g)*40 + ks + 2*tg];
            uint32_t b1 = *(const uint32_t*)&Bs[(nt*8+g)*40 + ks + 2*tg + 8];
            MMA_BF16(acc[nt], a0, a1, a2, a3, b0, b1);
        }
    }
    int row0 = rowbase + mrow + g;
    int row1 = row0 + 8;
    #pragma unroll
    for (int nt = 0; nt < 16; nt++) {
        int c = nt*8 + 2*tg;
        *(__nv_bfloat162*)&d_h2b[(size_t)row0*EMB + c] =
            __floats2bfloat162_rn(fmaxf(acc[nt][0], 0.f), fmaxf(acc[nt][1], 0.f));
        *(__nv_bfloat162*)&d_h2b[(size_t)row1*EMB + c] =
            __floats2bfloat162_rn(fmaxf(acc[nt][2], 0.f), fmaxf(acc[nt][3], 0.f));
    }
}

// ---------------- 6: gcn2 matmul bf16 mma (spill-free: 2 blocks/SM) -------------------
__global__ void __launch_bounds__(256, 2) k_mm2b(const float* __restrict__ bias) {
    __shared__ __nv_bfloat16 As[128*40];
    __shared__ __nv_bfloat16 Bs[128*40];
    int tid = threadIdx.x;
    int wid = tid >> 5, lane = tid & 31;
    int g = lane >> 2, tg = lane & 3;
    int rowbase = blockIdx.x * 128;
    int mrow = wid * 16;

    float acc[16][4];
    #pragma unroll
    for (int nt = 0; nt < 16; nt++) {
        int c = nt*8 + 2*tg;
        float b0 = bias[c], b1 = bias[c+1];
        acc[nt][0] = b0; acc[nt][1] = b1; acc[nt][2] = b0; acc[nt][3] = b1;
    }
    for (int kc = 0; kc < 4; kc++) {
        #pragma unroll
        for (int i = tid; i < 512; i += 256) {
            int r = i >> 2, k8 = (i & 3) * 8;
            *(uint4*)&As[r*40 + k8] =
                *(const uint4*)&d_a2b[(size_t)(rowbase + r)*EMB + kc*32 + k8];
        }
        #pragma unroll
        for (int i = tid; i < 512; i += 256) {
            int r = i >> 2, k8 = (i & 3) * 8;
            *(uint4*)&Bs[r*40 + k8] = *(const uint4*)&d_w2tb[r*EMB + kc*32 + k8];
        }
        __syncthreads();
        #pragma unroll
        for (int ks = 0; ks < 32; ks += 16) {
            uint32_t a0 = *(const uint32_t*)&As[(mrow+g  )*40 + ks + 2*tg];
            uint32_t a1 = *(const uint32_t*)&As[(mrow+g+8)*40 + ks + 2*tg];
            uint32_t a2 = *(const uint32_t*)&As[(mrow+g  )*40 + ks + 2*tg + 8];
            uint32_t a3 = *(const uint32_t*)&As[(mrow+g+8)*40 + ks + 2*tg + 8];
            #pragma unroll
            for (int nt = 0; nt < 16; nt++) {
                uint32_t b0 = *(const uint32_t*)&Bs[(nt*8+g)*40 + ks + 2*tg];
                uint32_t b1 = *(const uint32_t*)&Bs[(nt*8+g)*40 + ks + 2*tg + 8];
                MMA_BF16(acc[nt], a0, a1, a2, a3, b0, b1);
            }
        }
        __syncthreads();
    }
    int row0 = rowbase + mrow + g;
    int row1 = row0 + 8;
    #pragma unroll
    for (int nt = 0; nt < 16; nt++) {
        int c = nt*8 + 2*tg;
        *(__nv_bfloat162*)&d_h2b[(size_t)row0*EMB + c] =
            __floats2bfloat162_rn(fmaxf(acc[nt][0], 0.f), fmaxf(acc[nt][1], 0.f));
        *(__nv_bfloat162*)&d_h2b[(size_t)row1*EMB + c] =
            __floats2bfloat162_rn(fmaxf(acc[nt][2], 0.f), fmaxf(acc[nt][3], 0.f));
    }
}

// ---------------- 7: conv2+bn2+pool+relu GEMM, fused graph-pool epilogue --------------
__global__ void __launch_bounds__(256, 2) k_conv2b(const int* __restrict__ batch) {
    __shared__ __nv_bfloat16 As[128*72];   // 18KB
    __shared__ __nv_bfloat16 Bs[64*72];    // 9KB
    int tid = threadIdx.x;
    int wid = tid >> 5, lane = tid & 31;
    int g = lane >> 2, tg = lane & 3;
    int n0 = blockIdx.x * 8;
    int mrow = wid * 16;

    float acc[8][4];
    #pragma unroll
    for (int nt = 0; nt < 8; nt++) {
        int c = nt*8 + 2*tg;
        float b0 = d_beff2[c], b1 = d_beff2[c+1];
        acc[nt][0] = b0; acc[nt][1] = b1; acc[nt][2] = b0; acc[nt][3] = b1;
    }
    for (int u = 0; u < 10; u++) {
        for (int h = 0; h < 2; h++) {
            #pragma unroll
            for (int i = tid; i < 1024; i += 256) {
                int r = i >> 3, k8 = (i & 7) * 8;
                uint4 v = make_uint4(0u, 0u, 0u, 0u);
                if (r < 112) {
                    int nl = r / 14, p = r - nl*14;
                    v = *(const uint4*)
                        &d_h2b[(size_t)((n0+nl)*TT + 4*p + u)*EMB + h*64 + k8];
                }
                *(uint4*)&As[r*72 + k8] = v;
            }
            #pragma unroll
            for (int i = tid; i < 512; i += 256) {
                int c = i >> 3, k8 = (i & 7) * 8;
                *(uint4*)&Bs[c*72 + k8] =
                    *(const uint4*)&d_weff2tb[(size_t)c*1280 + u*128 + h*64 + k8];
            }
            __syncthreads();
            #pragma unroll
            for (int ks = 0; ks < 64; ks += 16) {
                uint32_t a0 = *(const uint32_t*)&As[(mrow+g  )*72 + ks + 2*tg];
                uint32_t a1 = *(const uint32_t*)&As[(mrow+g+8)*72 + ks + 2*tg];
                uint32_t a2 = *(const uint32_t*)&As[(mrow+g  )*72 + ks + 2*tg + 8];
                uint32_t a3 = *(const uint32_t*)&As[(mrow+g+8)*72 + ks + 2*tg + 8];
                #pragma unroll
                for (int nt = 0; nt < 8; nt++) {
                    uint32_t b0 = *(const uint32_t*)&Bs[(nt*8+g)*72 + ks + 2*tg];
                    uint32_t b1 = *(const uint32_t*)&Bs[(nt*8+g)*72 + ks + 2*tg + 8];
                    MMA_BF16(acc[nt], a0, a1, a2, a3, b0, b1);
                }
            }
            __syncthreads();
        }
    }
    int r0 = mrow + g;
    if (r0 < 112) {
        int nl0 = r0 / 14, p0 = r0 - nl0*14;
        int base0 = batch[n0 + nl0]*(14*C1) + p0*C1;
        int r1 = r0 + 8;
        int nl1 = r1 / 14, p1 = r1 - nl1*14;
        int base1 = batch[n0 + nl1]*(14*C1) + p1*C1;
        #pragma unroll
        for (int nt = 0; nt < 8; nt++) {
            int c = nt*8 + 2*tg;
            atomicAdd(&d_gp[base0 + c],     fmaxf(acc[nt][0], 0.f));
            atomicAdd(&d_gp[base0 + c + 1], fmaxf(acc[nt][1], 0.f));
            atomicAdd(&d_gp[base1 + c],     fmaxf(acc[nt][2], 0.f));
            atomicAdd(&d_gp[base1 + c + 1], fmaxf(acc[nt][3], 0.f));
        }
    }
}

// ---------------- 8: conv3+bn3+pool+relu + dense + log_softmax (+restore d_gp zero) ---
__global__ void __launch_bounds__(128) k_final(const int* __restrict__ batch,
                                               const float* __restrict__ dw,
                                               const float* __restrict__ db,
                                               float* __restrict__ out) {
    __shared__ float gin[14*C1];
    __shared__ float flat[128];
    __shared__ float lg[4];
    __shared__ int scount;
    int b = blockIdx.x, tid = threadIdx.x;
    if (tid == 0) scount = 0;
    __syncthreads();
    int cnt = 0;
    for (int i = tid; i < NN; i += 128) cnt += (batch[i] == b);
    #pragma unroll
    for (int s = 16; s > 0; s >>= 1) cnt += __shfl_down_sync(0xffffffffu, cnt, s);
    if ((tid & 31) == 0) atomicAdd(&scount, cnt);
    for (int i = tid; i < 14*C1; i += 128) gin[i] = d_gp[b*14*C1 + i];
    __syncthreads();
    float inv = 1.f / (float)scount;
    for (int i = tid; i < 14*C1; i += 128) d_gp[b*14*C1 + i] = 0.f;
    int p = tid >> 6, c = tid & 63;
    float acc = d_beff3[c];
    for (int u = 0; u < 10; u++)
        for (int ci = 0; ci < C2; ci++)
            acc += gin[(4*p + u)*C2 + ci] * inv * d_weff3[(u*C2 + ci)*C2 + c];
    flat[p*64 + c] = fmaxf(acc, 0.f);
    __syncthreads();
    if (tid < 4) {
        float a = db[tid];
        for (int i = 0; i < 128; i++) a += flat[i] * dw[i*4 + tid];
        lg[tid] = a;
    }
    __syncthreads();
    if (tid == 0) {
        float m = fmaxf(fmaxf(lg[0], lg[1]), fmaxf(lg[2], lg[3]));
        float se = expf(lg[0]-m) + expf(lg[1]-m) + expf(lg[2]-m) + expf(lg[3]-m);
        float lse = logf(se) + m;
        for (int j = 0; j < 4; j++) out[b*4 + j] = lg[j] - lse;
    }
}

// ---------------- launcher ----------------
extern "C" void kernel_launch(void* const* d_in, const int* in_sizes, int n_in,
                              void* d_out, int out_size) {
    const float* x       = (const float*)d_in[0];
    const int*   edge    = (const int*)d_in[1];
    const int*   batch   = (const int*)d_in[2];
    const float* conv1_w = (const float*)d_in[3];
    const float* bn1_g   = (const float*)d_in[4];
    const float* bn1_b   = (const float*)d_in[5];
    const float* bn1_m   = (const float*)d_in[6];
    const float* bn1_v   = (const float*)d_in[7];
    const float* gcn1_w  = (const float*)d_in[8];
    const float* gcn1_b  = (const float*)d_in[9];
    const float* gcn2_w  = (const float*)d_in[10];
    const float* gcn2_b  = (const float*)d_in[11];
    const float* conv2_w = (const float*)d_in[12];
    const float* bn2_g   = (const float*)d_in[13];
    const float* bn2_b   = (const float*)d_in[14];
    const float* bn2_m   = (const float*)d_in[15];
    const float* bn2_v   = (const float*)d_in[16];
    const float* conv3_w = (const float*)d_in[17];
    const float* bn3_g   = (const float*)d_in[18];
    const float* bn3_b   = (const float*)d_in[19];
    const float* bn3_m   = (const float*)d_in[20];
    const float* bn3_v   = (const float*)d_in[21];
    const float* dense_w = (const float*)d_in[22];
    const float* dense_b = (const float*)d_in[23];
    float* out = (float*)d_out;

    k_prep<<<320, 256>>>(edge, gcn1_w, gcn2_w,
                         conv2_w, bn2_g, bn2_b, bn2_m, bn2_v,
                         conv3_w, bn3_g, bn3_b, bn3_m, bn3_v);
    k_conv1sc<<<NN + 32, 128>>>(x, conv1_w, bn1_g, bn1_b, bn1_m, bn1_v, edge);
    k_agg1b<<<NN, 256>>>();
    k_mm1b<<<1024, 256>>>(gcn1_b);
    k_agg2b<<<dim3(NN, 4), 256>>>();
    k_mm2b<<<1024, 256>>>(gcn2_b);
    k_conv2b<<<256, 256>>>(batch);
    k_final<<<BB, 128>>>(batch, dense_w, dense_b, out);
}

// round 12
// speedup vs baseline: 1.0224x; 1.0088x over previous
#include <cuda_runtime.h>
#include <cuda_bf16.h>
#include <math.h>
#include <stdint.h>

#define NN  2048
#define TT  64
#define EE  16384
#define BB  64
#define C0  32
#define EMB 128
#define C1  64
#define C2  64
#define EPSB 1e-5f

// ---------------- scratch (device globals; BSS -> zero at load) ----------------
__device__ __nv_bfloat16 d_h1b[NN*TT*C0];    // conv1 out (8MB)
__device__ __nv_bfloat16 d_a1b[NN*TT*C0];    // agg1 out  (8MB)
__device__ __nv_bfloat16 d_h2b[NN*TT*EMB];   // gcn1/gcn2 out (32MB)
__device__ __nv_bfloat16 d_a2b[NN*TT*EMB];   // agg2 out  (32MB)
__device__ float d_gp[BB*14*C1];             // INVARIANT: zero at entry (k_final re-zeros)
__device__ int   d_rowcnt[NN];               // INVARIANT: zero at entry (prep last block re-zeros)
__device__ unsigned d_done;                  // INVARIANT: zero at entry (prep last block re-zeros)
__device__ int   d_rowstart[NN+1];
__device__ int   d_cursor[NN];
__device__ int   d_csrsrc[EE];
__device__ float d_dinv[NN];
__device__ __nv_bfloat16 d_w1tb[EMB*C0];       // gcn1 W transposed [n][k] bf16
__device__ __nv_bfloat16 d_w2tb[EMB*EMB];      // gcn2 W transposed [n][k] bf16
__device__ __nv_bfloat16 d_weff2tb[C1*1280];   // conv2 eff W transposed [c][u*128+ci] bf16
__device__ float d_beff2[C1];
__device__ float d_weff3[10*C2*C2];
__device__ float d_beff3[C2];

// ---------------- 1: prep (weight folds + degree count) + LAST-BLOCK scan ------------
__global__ void __launch_bounds__(256) k_prep(const int* __restrict__ edge,
                       const float* __restrict__ w1, const float* __restrict__ wg2,
                       const float* __restrict__ w2, const float* __restrict__ g2,
                       const float* __restrict__ b2, const float* __restrict__ m2,
                       const float* __restrict__ v2,
                       const float* __restrict__ w3, const float* __restrict__ g3,
                       const float* __restrict__ b3, const float* __restrict__ m3,
                       const float* __restrict__ v3) {
    __shared__ int sc[NN];       // per-chunk inclusive scans (last block only)
    __shared__ int st[256];
    __shared__ bool s_last;
    int tid = threadIdx.x;
    int i = blockIdx.x * blockDim.x + tid;
    if (i < EE) atomicAdd(&d_rowcnt[edge[EE + i]], 1);   // d_rowcnt zero by invariant
    if (i < C1) { float s = g2[i]*rsqrtf(v2[i]+EPSB); d_beff2[i]=b2[i]-m2[i]*s; }
    if (i < C2) { float s = g3[i]*rsqrtf(v3[i]+EPSB); d_beff3[i]=b3[i]-m3[i]*s; }
    if (i < EMB*C0) {
        int n = i >> 5, k = i & 31;
        d_w1tb[i] = __float2bfloat16(w1[k*EMB + n]);
    }
    if (i < EMB*EMB) {
        int n = i >> 7, k = i & 127;
        d_w2tb[i] = __float2bfloat16(wg2[k*EMB + n]);
    }
    if (i < C1*1280) {
        int c = i / 1280, kk = i - c*1280;
        int u = kk >> 7, ci = kk & 127;
        float s = g2[c]*rsqrtf(v2[c]+EPSB);
        int klo = u-3; if (klo < 0) klo = 0;
        int khi = u < 6 ? u : 6;
        float acc = 0.f;
        for (int k = klo; k <= khi; k++) acc += w2[(k*EMB+ci)*C1 + c];
        d_weff2tb[i] = __float2bfloat16(acc * s * 0.25f);
    }
    if (i < 10*C2*C2) {
        int c = i % C2; int ci = (i / C2) % C2; int u = i / (C2*C2);
        float s = g3[c]*rsqrtf(v3[c]+EPSB);
        int klo = u-3; if (klo < 0) klo = 0;
        int khi = u < 6 ? u : 6;
        float acc = 0.f;
        for (int k = klo; k <= khi; k++) acc += w3[(k*C2+ci)*C2 + c];
        d_weff3[i] = acc * s * 0.25f;
    }
    // ---- last-block-done: run the CSR scan once all degree atomics are visible ----
    __syncthreads();
    if (tid == 0) {
        __threadfence();
        unsigned t = atomicAdd(&d_done, 1u);
        s_last = (t == gridDim.x - 1);
    }
    __syncthreads();
    if (!s_last) return;

    int base = tid * 8;
    int run = 0;
    #pragma unroll
    for (int j = 0; j < 8; j++) {
        int c = d_rowcnt[base + j];
        d_rowcnt[base + j] = 0;                       // restore invariant
        d_dinv[base + j] = rsqrtf((float)(c + 1));
        run += c;
        sc[base + j] = run;                           // inclusive within chunk
    }
    st[tid] = run;
    __syncthreads();
    for (int off = 1; off < 256; off <<= 1) {
        int v = (tid >= off) ? st[tid - off] : 0;
        __syncthreads();
        st[tid] += v;
        __syncthreads();
    }
    int chunk_excl = (tid == 0) ? 0 : st[tid - 1];
    #pragma unroll
    for (int j = 0; j < 8; j++) {
        int excl = chunk_excl + ((j == 0) ? 0 : sc[base + j - 1]);
        d_rowstart[base + j] = excl;
        d_cursor[base + j]   = excl;
    }
    if (tid == 255) {
        d_rowstart[NN] = chunk_excl + sc[base + 7];   // total = EE
        d_done = 0;                                   // restore invariant
    }
}

// ---------------- 2: conv1(+inline bn1 fold) for blocks<NN; CSR scatter on the rest --
__global__ void __launch_bounds__(128) k_conv1sc(const float* __restrict__ x,
                                                const float* __restrict__ w,
                                                const float* __restrict__ g1,
                                                const float* __restrict__ b1,
                                                const float* __restrict__ m1,
                                                const float* __restrict__ v1,
                                                const int* __restrict__ edge) {
    int blk = blockIdx.x, tid = threadIdx.x;
    if (blk >= NN) {
        for (int e = (blk - NN)*128 + tid; e < EE; e += 32*128) {
            int dd = edge[EE + e];
            int pos = atomicAdd(&d_cursor[dd], 1);
            d_csrsrc[pos] = edge[e];
        }
        return;
    }
    __shared__ float xs[TT + 6];
    __shared__ float ws[7*C0];
    __shared__ float ss[C0], bs[C0];
    int n = blk;
    if (tid < TT) xs[tid + 3] = x[n*TT + tid];
    if (tid < 3)  { xs[tid] = 0.f; xs[TT + 3 + tid] = 0.f; }
    for (int i = tid; i < 7*C0; i += 128) ws[i] = w[i];
    if (tid < C0) {
        float s = g1[tid]*rsqrtf(v1[tid]+EPSB);
        ss[tid] = s; bs[tid] = b1[tid] - m1[tid]*s;
    }
    __syncthreads();
    int t = tid >> 1, cb = (tid & 1) * 16;
    float acc[16];
    #pragma unroll
    for (int c = 0; c < 16; c++) acc[c] = 0.f;
    #pragma unroll
    for (int k = 0; k < 7; k++) {
        float xv = xs[t + k];
        #pragma unroll
        for (int c = 0; c < 16; c++) acc[c] += xv * ws[k*C0 + cb + c];
    }
    uint4 o[2];
    __nv_bfloat162* ob = (__nv_bfloat162*)o;
    #pragma unroll
    for (int j = 0; j < 8; j++) {
        float f0 = fmaxf(acc[2*j]   * ss[cb+2*j]   + bs[cb+2*j],   0.f);
        float f1 = fmaxf(acc[2*j+1] * ss[cb+2*j+1] + bs[cb+2*j+1], 0.f);
        ob[j] = __floats2bfloat162_rn(f0, f1);
    }
    __nv_bfloat16* dst = &d_h1b[(n*TT + t)*C0 + cb];
    *(uint4*)dst = o[0];
    *(uint4*)(dst + 8) = o[1];
}

// ---------------- helpers ----------------
__device__ __forceinline__ void acc_u4(float* a, uint4 v, float w) {
    const __nv_bfloat162* b = (const __nv_bfloat162*)&v;
    #pragma unroll
    for (int j = 0; j < 4; j++) {
        float2 f = __bfloat1622float2(b[j]);
        a[2*j]   += w * f.x;
        a[2*j+1] += w * f.y;
    }
}
__device__ __forceinline__ void store_row8(__nv_bfloat16* p, const float* a, float sc) {
    uint4 o;
    __nv_bfloat162* b = (__nv_bfloat162*)&o;
    #pragma unroll
    for (int j = 0; j < 4; j++) b[j] = __floats2bfloat162_rn(a[2*j]*sc, a[2*j+1]*sc);
    *(uint4*)p = o;
}

// ---------------- 3: agg1 (bf16), 4-edge ILP gather ----------------
__global__ void __launch_bounds__(256) k_agg1b() {
    int node = blockIdx.x;
    int off  = threadIdx.x * 8;
    float di = d_dinv[node];
    float a[8] = {0,0,0,0,0,0,0,0};
    {
        uint4 v = *(const uint4*)(d_h1b + (size_t)node*2048 + off);
        acc_u4(a, v, di);
    }
    int e0 = d_rowstart[node], e1 = d_rowstart[node+1];
    int e = e0;
    for (; e + 4 <= e1; e += 4) {
        int s0 = d_csrsrc[e], s1 = d_csrsrc[e+1], s2 = d_csrsrc[e+2], s3 = d_csrsrc[e+3];
        float w0 = d_dinv[s0], w1 = d_dinv[s1], w2 = d_dinv[s2], w3 = d_dinv[s3];
        uint4 v0 = *(const uint4*)(d_h1b + (size_t)s0*2048 + off);
        uint4 v1 = *(const uint4*)(d_h1b + (size_t)s1*2048 + off);
        uint4 v2 = *(const uint4*)(d_h1b + (size_t)s2*2048 + off);
        uint4 v3 = *(const uint4*)(d_h1b + (size_t)s3*2048 + off);
        acc_u4(a, v0, w0); acc_u4(a, v1, w1); acc_u4(a, v2, w2); acc_u4(a, v3, w3);
    }
    for (; e < e1; e++) {
        int s = d_csrsrc[e];
        float w = d_dinv[s];
        uint4 v = *(const uint4*)(d_h1b + (size_t)s*2048 + off);
        acc_u4(a, v, w);
    }
    store_row8(d_a1b + (size_t)node*2048 + off, a, di);
}

// ---------------- 5: agg2 (bf16), grid.y=4, 4-edge ILP gather ----------------
__global__ void __launch_bounds__(256) k_agg2b() {
    int node = blockIdx.x;
    int off  = blockIdx.y*2048 + threadIdx.x * 8;
    float di = d_dinv[node];
    float a[8] = {0,0,0,0,0,0,0,0};
    {
        uint4 v = *(const uint4*)(d_h2b + (size_t)node*8192 + off);
        acc_u4(a, v, di);
    }
    int e0 = d_rowstart[node], e1 = d_rowstart[node+1];
    int e = e0;
    for (; e + 4 <= e1; e += 4) {
        int s0 = d_csrsrc[e], s1 = d_csrsrc[e+1], s2 = d_csrsrc[e+2], s3 = d_csrsrc[e+3];
        float w0 = d_dinv[s0], w1 = d_dinv[s1], w2 = d_dinv[s2], w3 = d_dinv[s3];
        uint4 v0 = *(const uint4*)(d_h2b + (size_t)s0*8192 + off);
        uint4 v1 = *(const uint4*)(d_h2b + (size_t)s1*8192 + off);
        uint4 v2 = *(const uint4*)(d_h2b + (size_t)s2*8192 + off);
        uint4 v3 = *(const uint4*)(d_h2b + (size_t)s3*8192 + off);
        acc_u4(a, v0, w0); acc_u4(a, v1, w1); acc_u4(a, v2, w2); acc_u4(a, v3, w3);
    }
    for (; e < e1; e++) {
        int s = d_csrsrc[e];
        float w = d_dinv[s];
        uint4 v = *(const uint4*)(d_h2b + (size_t)s*8192 + off);
        acc_u4(a, v, w);
    }
    store_row8(d_a2b + (size_t)node*8192 + off, a, di);
}

// ---------------- bf16 mma macro ----------------
#define MMA_BF16(acc, A0, A1, A2, A3, B0, B1)                                   \
    asm volatile(                                                               \
        "mma.sync.aligned.m16n8k16.row.col.f32.bf16.bf16.f32 "                  \
        "{%0,%1,%2,%3}, {%4,%5,%6,%7}, {%8,%9}, {%0,%1,%2,%3};"                 \
        : "+f"(acc[0]), "+f"(acc[1]), "+f"(acc[2]), "+f"(acc[3])                \
        : "r"(A0), "r"(A1), "r"(A2), "r"(A3), "r"(B0), "r"(B1))

// Coalesced epilogue: stage 64 rows at a time in smem (stride 136, conflict-free),
// then 16B coalesced stores. S must be >= 64*136 elements; As/Bs are dead by now.
#define EPILOGUE_STORE(S_, acc_, NTN, dst_, rowbase_)                            \
    for (int half = 0; half < 2; half++) {                                       \
        __syncthreads();                                                         \
        if ((wid >> 2) == half) {                                                \
            int lr = (mrow & 63) + g;                                            \
            _Pragma("unroll")                                                    \
            for (int nt = 0; nt < NTN; nt++) {                                   \
                int c = nt*8 + 2*tg;                                             \
                *(__nv_bfloat162*)&S_[lr*136 + c] =                              \
                    __floats2bfloat162_rn(fmaxf(acc_[nt][0], 0.f),               \
                                          fmaxf(acc_[nt][1], 0.f));              \
                *(__nv_bfloat162*)&S_[(lr+8)*136 + c] =                          \
                    __floats2bfloat162_rn(fmaxf(acc_[nt][2], 0.f),               \
                                          fmaxf(acc_[nt][3], 0.f));              \
            }                                                                    \
        }                                                                        \
        __syncthreads();                                                         \
        _Pragma("unroll")                                                        \
        for (int i = tid; i < 1024; i += 256) {                                  \
            int r = i >> 4, c8 = (i & 15) * 8;                                   \
            *(uint4*)&dst_[(size_t)(rowbase_ + half*64 + r)*EMB + c8] =          \
                *(const uint4*)&S_[r*136 + c8];                                  \
        }                                                                        \
    }

// ---------------- 4: gcn1 matmul bf16 mma, coalesced epilogue -------------------------
__global__ void __launch_bounds__(256, 3) k_mm1b(const float* __restrict__ bias) {
    __shared__ __nv_bfloat16 S[10240];       // As[0:5120) | Bs[5120:10240); epilogue reuses
    __nv_bfloat16* As = S;
    __nv_bfloat16* Bs = S + 5120;
    int tid = threadIdx.x;
    int wid = tid >> 5, lane = tid & 31;
    int g = lane >> 2, tg = lane & 3;
    int rowbase = blockIdx.x * 128;
    int mrow = wid * 16;

    float acc[16][4];
    #pragma unroll
    for (int nt = 0; nt < 16; nt++) {
        int c = nt*8 + 2*tg;
        float b0 = bias[c], b1 = bias[c+1];
        acc[nt][0] = b0; acc[nt][1] = b1; acc[nt][2] = b0; acc[nt][3] = b1;
    }
    #pragma unroll
    for (int i = tid; i < 512; i += 256) {
        int r = i >> 2, k8 = (i & 3) * 8;
        *(uint4*)&As[r*40 + k8] = *(const uint4*)&d_a1b[(size_t)(rowbase + r)*C0 + k8];
    }
    #pragma unroll
    for (int i = tid; i < 512; i += 256) {
        int r = i >> 2, k8 = (i & 3) * 8;
        *(uint4*)&Bs[r*40 + k8] = *(const uint4*)&d_w1tb[r*C0 + k8];
    }
    __syncthreads();
    #pragma unroll
    for (int ks = 0; ks < 32; ks += 16) {
        uint32_t a0 = *(const uint32_t*)&As[(mrow+g  )*40 + ks + 2*tg];
        uint32_t a1 = *(const uint32_t*)&As[(mrow+g+8)*40 + ks + 2*tg];
        uint32_t a2 = *(const uint32_t*)&As[(mrow+g  )*40 + ks + 2*tg + 8];
        uint32_t a3 = *(const uint32_t*)&As[(mrow+g+8)*40 + ks + 2*tg + 8];
        #pragma unroll
        for (int nt = 0; nt < 16; nt++) {
            uint32_t b0 = *(const uint32_t*)&Bs[(nt*8+g)*40 + ks + 2*tg];
            uint32_t b1 = *(const uint32_t*)&Bs[(nt*8+g)*40 + ks + 2*tg + 8];
            MMA_BF16(acc[nt], a0, a1, a2, a3, b0, b1);
        }
    }
    EPILOGUE_STORE(S, acc, 16, d_h2b, rowbase)
}

// ---------------- 6: gcn2 matmul bf16 mma, coalesced epilogue -------------------------
__global__ void __launch_bounds__(256, 3) k_mm2b(const float* __restrict__ bias) {
    __shared__ __nv_bfloat16 S[10240];
    __nv_bfloat16* As = S;
    __nv_bfloat16* Bs = S + 5120;
    int tid = threadIdx.x;
    int wid = tid >> 5, lane = tid & 31;
    int g = lane >> 2, tg = lane & 3;
    int rowbase = blockIdx.x * 128;
    int mrow = wid * 16;

    float acc[16][4];
    #pragma unroll
    for (int nt = 0; nt < 16; nt++) {
        int c = nt*8 + 2*tg;
        float b0 = bias[c], b1 = bias[c+1];
        acc[nt][0] = b0; acc[nt][1] = b1; acc[nt][2] = b0; acc[nt][3] = b1;
    }
    for (int kc = 0; kc < 4; kc++) {
        #pragma unroll
        for (int i = tid; i < 512; i += 256) {
            int r = i >> 2, k8 = (i & 3) * 8;
            *(uint4*)&As[r*40 + k8] =
                *(const uint4*)&d_a2b[(size_t)(rowbase + r)*EMB + kc*32 + k8];
        }
        #pragma unroll
        for (int i = tid; i < 512; i += 256) {
            int r = i >> 2, k8 = (i & 3) * 8;
            *(uint4*)&Bs[r*40 + k8] = *(const uint4*)&d_w2tb[r*EMB + kc*32 + k8];
        }
        __syncthreads();
        #pragma unroll
        for (int ks = 0; ks < 32; ks += 16) {
            uint32_t a0 = *(const uint32_t*)&As[(mrow+g  )*40 + ks + 2*tg];
            uint32_t a1 = *(const uint32_t*)&As[(mrow+g+8)*40 + ks + 2*tg];
            uint32_t a2 = *(const uint32_t*)&As[(mrow+g  )*40 + ks + 2*tg + 8];
            uint32_t a3 = *(const uint32_t*)&As[(mrow+g+8)*40 + ks + 2*tg + 8];
            #pragma unroll
            for (int nt = 0; nt < 16; nt++) {
                uint32_t b0 = *(const uint32_t*)&Bs[(nt*8+g)*40 + ks + 2*tg];
                uint32_t b1 = *(const uint32_t*)&Bs[(nt*8+g)*40 + ks + 2*tg + 8];
                MMA_BF16(acc[nt], a0, a1, a2, a3, b0, b1);
            }
        }
        __syncthreads();
    }
    EPILOGUE_STORE(S, acc, 16, d_h2b, rowbase)
}

// ---------------- 7: conv2+bn2+pool+relu GEMM, fused graph-pool epilogue --------------
__global__ void __launch_bounds__(256, 2) k_conv2b(const int* __restrict__ batch) {
    __shared__ __nv_bfloat16 As[128*72];   // 18KB
    __shared__ __nv_bfloat16 Bs[64*72];    // 9KB
    int tid = threadIdx.x;
    int wid = tid >> 5, lane = tid & 31;
    int g = lane >> 2, tg = lane & 3;
    int n0 = blockIdx.x * 8;
    int mrow = wid * 16;

    float acc[8][4];
    #pragma unroll
    for (int nt = 0; nt < 8; nt++) {
        int c = nt*8 + 2*tg;
        float b0 = d_beff2[c], b1 = d_beff2[c+1];
        acc[nt][0] = b0; acc[nt][1] = b1; acc[nt][2] = b0; acc[nt][3] = b1;
    }
    for (int u = 0; u < 10; u++) {
        for (int h = 0; h < 2; h++) {
            #pragma unroll
            for (int i = tid; i < 1024; i += 256) {
                int r = i >> 3, k8 = (i & 7) * 8;
                uint4 v = make_uint4(0u, 0u, 0u, 0u);
                if (r < 112) {
                    int nl = r / 14, p = r - nl*14;
                    v = *(const uint4*)
                        &d_h2b[(size_t)((n0+nl)*TT + 4*p + u)*EMB + h*64 + k8];
                }
                *(uint4*)&As[r*72 + k8] = v;
            }
            #pragma unroll
            for (int i = tid; i < 512; i += 256) {
                int c = i >> 3, k8 = (i & 7) * 8;
                *(uint4*)&Bs[c*72 + k8] =
                    *(const uint4*)&d_weff2tb[(size_t)c*1280 + u*128 + h*64 + k8];
            }
            __syncthreads();
            #pragma unroll
            for (int ks = 0; ks < 64; ks += 16) {
                uint32_t a0 = *(const uint32_t*)&As[(mrow+g  )*72 + ks + 2*tg];
                uint32_t a1 = *(const uint32_t*)&As[(mrow+g+8)*72 + ks + 2*tg];
                uint32_t a2 = *(const uint32_t*)&As[(mrow+g  )*72 + ks + 2*tg + 8];
                uint32_t a3 = *(const uint32_t*)&As[(mrow+g+8)*72 + ks + 2*tg + 8];
                #pragma unroll
                for (int nt = 0; nt < 8; nt++) {
                    uint32_t b0 = *(const uint32_t*)&Bs[(nt*8+g)*72 + ks + 2*tg];
                    uint32_t b1 = *(const uint32_t*)&Bs[(nt*8+g)*72 + ks + 2*tg + 8];
                    MMA_BF16(acc[nt], a0, a1, a2, a3, b0, b1);
                }
            }
            __syncthreads();
        }
    }
    int r0 = mrow + g;
    if (r0 < 112) {
        int nl0 = r0 / 14, p0 = r0 - nl0*14;
        int base0 = batch[n0 + nl0]*(14*C1) + p0*C1;
        int r1 = r0 + 8;
        int nl1 = r1 / 14, p1 = r1 - nl1*14;
        int base1 = batch[n0 + nl1]*(14*C1) + p1*C1;
        #pragma unroll
        for (int nt = 0; nt < 8; nt++) {
            int c = nt*8 + 2*tg;
            atomicAdd(&d_gp[base0 + c],     fmaxf(acc[nt][0], 0.f));
            atomicAdd(&d_gp[base0 + c + 1], fmaxf(acc[nt][1], 0.f));
            atomicAdd(&d_gp[base1 + c],     fmaxf(acc[nt][2], 0.f));
            atomicAdd(&d_gp[base1 + c + 1], fmaxf(acc[nt][3], 0.f));
        }
    }
}

// ---------------- 8: conv3+bn3+pool+relu + dense + log_softmax (+restore d_gp zero) ---
__global__ void __launch_bounds__(128) k_final(const int* __restrict__ batch,
                                               const float* __restrict__ dw,
                                               const float* __restrict__ db,
                                               float* __restrict__ out) {
    __shared__ float gin[14*C1];
    __shared__ float flat[128];
    __shared__ float lg[4];
    __shared__ int scount;
    int b = blockIdx.x, tid = threadIdx.x;
    if (tid == 0) scount = 0;
    __syncthreads();
    int cnt = 0;
    for (int i = tid; i < NN; i += 128) cnt += (batch[i] == b);
    #pragma unroll
    for (int s = 16; s > 0; s >>= 1) cnt += __shfl_down_sync(0xffffffffu, cnt, s);
    if ((tid & 31) == 0) atomicAdd(&scount, cnt);
    for (int i = tid; i < 14*C1; i += 128) gin[i] = d_gp[b*14*C1 + i];
    __syncthreads();
    float inv = 1.f / (float)scount;
    for (int i = tid; i < 14*C1; i += 128) d_gp[b*14*C1 + i] = 0.f;
    int p = tid >> 6, c = tid & 63;
    float acc = d_beff3[c];
    for (int u = 0; u < 10; u++)
        for (int ci = 0; ci < C2; ci++)
            acc += gin[(4*p + u)*C2 + ci] * inv * d_weff3[(u*C2 + ci)*C2 + c];
    flat[p*64 + c] = fmaxf(acc, 0.f);
    __syncthreads();
    if (tid < 4) {
        float a = db[tid];
        for (int i = 0; i < 128; i++) a += flat[i] * dw[i*4 + tid];
        lg[tid] = a;
    }
    __syncthreads();
    if (tid == 0) {
        float m = fmaxf(fmaxf(lg[0], lg[1]), fmaxf(lg[2], lg[3]));
        float se = expf(lg[0]-m) + expf(lg[1]-m) + expf(lg[2]-m) + expf(lg[3]-m);
        float lse = logf(se) + m;
        for (int j = 0; j < 4; j++) out[b*4 + j] = lg[j] - lse;
    }
}

// ---------------- launcher ----------------
extern "C" void kernel_launch(void* const* d_in, const int* in_sizes, int n_in,
                              void* d_out, int out_size) {
    const float* x       = (const float*)d_in[0];
    const int*   edge    = (const int*)d_in[1];
    const int*   batch   = (const int*)d_in[2];
    const float* conv1_w = (const float*)d_in[3];
    const float* bn1_g   = (const float*)d_in[4];
    const float* bn1_b   = (const float*)d_in[5];
    const float* bn1_m   = (const float*)d_in[6];
    const float* bn1_v   = (const float*)d_in[7];
    const float* gcn1_w  = (const float*)d_in[8];
    const float* gcn1_b  = (const float*)d_in[9];
    const float* gcn2_w  = (const float*)d_in[10];
    const float* gcn2_b  = (const float*)d_in[11];
    const float* conv2_w = (const float*)d_in[12];
    const float* bn2_g   = (const float*)d_in[13];
    const float* bn2_b   = (const float*)d_in[14];
    const float* bn2_m   = (const float*)d_in[15];
    const float* bn2_v   = (const float*)d_in[16];
    const float* conv3_w = (const float*)d_in[17];
    const float* bn3_g   = (const float*)d_in[18];
    const float* bn3_b   = (const float*)d_in[19];
    const float* bn3_m   = (const float*)d_in[20];
    const float* bn3_v   = (const float*)d_in[21];
    const float* dense_w = (const float*)d_in[22];
    const float* dense_b = (const float*)d_in[23];
    float* out = (float*)d_out;

    k_prep<<<320, 256>>>(edge, gcn1_w, gcn2_w,
                         conv2_w, bn2_g, bn2_b, bn2_m, bn2_v,
                         conv3_w, bn3_g, bn3_b, bn3_m, bn3_v);
    k_conv1sc<<<NN + 32, 128>>>(x, conv1_w, bn1_g, bn1_b, bn1_m, bn1_v, edge);
    k_agg1b<<<NN, 256>>>();
    k_mm1b<<<1024, 256>>>(gcn1_b);
    k_agg2b<<<dim3(NN, 4), 256>>>();
    k_mm2b<<<1024, 256>>>(gcn2_b);
    k_conv2b<<<256, 256>>>(batch);
    k_final<<<BB, 128>>>(batch, dense_w, dense_b, out);
}

// round 13
// speedup vs baseline: 1.0311x; 1.0085x over previous
#include <cuda_runtime.h>
#include <cuda_bf16.h>
#include <math.h>
#include <stdint.h>

#define NN  2048
#define TT  64
#define EE  16384
#define BB  64
#define C0  32
#define EMB 128
#define C1  64
#define C2  64
#define EPSB 1e-5f

// ---------------- scratch (device globals; BSS -> zero at load) ----------------
__device__ __nv_bfloat16 d_h1b[NN*TT*C0];    // conv1 out (8MB)
__device__ __nv_bfloat16 d_h2b[NN*TT*EMB];   // gcn1/gcn2 out (32MB)
__device__ __nv_bfloat16 d_a2b[NN*TT*EMB];   // agg2 out  (32MB)
__device__ float d_gp[BB*14*C1];             // INVARIANT: zero at entry (k_final re-zeros)
__device__ int   d_rowcnt[NN];               // INVARIANT: zero at entry (prep last block re-zeros)
__device__ unsigned d_done;                  // INVARIANT: zero at entry (prep last block re-zeros)
__device__ int   d_rowstart[NN+1];
__device__ int   d_cursor[NN];
__device__ int   d_csrsrc[EE];
__device__ float d_dinv[NN];
__device__ __nv_bfloat16 d_w1tb[EMB*C0];       // gcn1 W transposed [n][k] bf16
__device__ __nv_bfloat16 d_w2tb[EMB*EMB];      // gcn2 W transposed [n][k] bf16
__device__ __nv_bfloat16 d_weff2tb[C1*1280];   // conv2 eff W transposed [c][u*128+ci] bf16
__device__ float d_beff2[C1];
__device__ float d_weff3[10*C2*C2];
__device__ float d_beff3[C2];

// ---------------- 1: prep (weight folds + degree count) + LAST-BLOCK scan ------------
__global__ void __launch_bounds__(256) k_prep(const int* __restrict__ edge,
                       const float* __restrict__ w1, const float* __restrict__ wg2,
                       const float* __restrict__ w2, const float* __restrict__ g2,
                       const float* __restrict__ b2, const float* __restrict__ m2,
                       const float* __restrict__ v2,
                       const float* __restrict__ w3, const float* __restrict__ g3,
                       const float* __restrict__ b3, const float* __restrict__ m3,
                       const float* __restrict__ v3) {
    __shared__ int sc[NN];
    __shared__ int st[256];
    __shared__ bool s_last;
    int tid = threadIdx.x;
    int i = blockIdx.x * blockDim.x + tid;
    if (i < EE) atomicAdd(&d_rowcnt[edge[EE + i]], 1);
    if (i < C1) { float s = g2[i]*rsqrtf(v2[i]+EPSB); d_beff2[i]=b2[i]-m2[i]*s; }
    if (i < C2) { float s = g3[i]*rsqrtf(v3[i]+EPSB); d_beff3[i]=b3[i]-m3[i]*s; }
    if (i < EMB*C0) {
        int n = i >> 5, k = i & 31;
        d_w1tb[i] = __float2bfloat16(w1[k*EMB + n]);
    }
    if (i < EMB*EMB) {
        int n = i >> 7, k = i & 127;
        d_w2tb[i] = __float2bfloat16(wg2[k*EMB + n]);
    }
    if (i < C1*1280) {
        int c = i / 1280, kk = i - c*1280;
        int u = kk >> 7, ci = kk & 127;
        float s = g2[c]*rsqrtf(v2[c]+EPSB);
        int klo = u-3; if (klo < 0) klo = 0;
        int khi = u < 6 ? u : 6;
        float acc = 0.f;
        for (int k = klo; k <= khi; k++) acc += w2[(k*EMB+ci)*C1 + c];
        d_weff2tb[i] = __float2bfloat16(acc * s * 0.25f);
    }
    if (i < 10*C2*C2) {
        int c = i % C2; int ci = (i / C2) % C2; int u = i / (C2*C2);
        float s = g3[c]*rsqrtf(v3[c]+EPSB);
        int klo = u-3; if (klo < 0) klo = 0;
        int khi = u < 6 ? u : 6;
        float acc = 0.f;
        for (int k = klo; k <= khi; k++) acc += w3[(k*C2+ci)*C2 + c];
        d_weff3[i] = acc * s * 0.25f;
    }
    __syncthreads();
    if (tid == 0) {
        __threadfence();
        unsigned t = atomicAdd(&d_done, 1u);
        s_last = (t == gridDim.x - 1);
    }
    __syncthreads();
    if (!s_last) return;

    int base = tid * 8;
    int run = 0;
    #pragma unroll
    for (int j = 0; j < 8; j++) {
        int c = d_rowcnt[base + j];
        d_rowcnt[base + j] = 0;
        d_dinv[base + j] = rsqrtf((float)(c + 1));
        run += c;
        sc[base + j] = run;
    }
    st[tid] = run;
    __syncthreads();
    for (int off = 1; off < 256; off <<= 1) {
        int v = (tid >= off) ? st[tid - off] : 0;
        __syncthreads();
        st[tid] += v;
        __syncthreads();
    }
    int chunk_excl = (tid == 0) ? 0 : st[tid - 1];
    #pragma unroll
    for (int j = 0; j < 8; j++) {
        int excl = chunk_excl + ((j == 0) ? 0 : sc[base + j - 1]);
        d_rowstart[base + j] = excl;
        d_cursor[base + j]   = excl;
    }
    if (tid == 255) {
        d_rowstart[NN] = chunk_excl + sc[base + 7];
        d_done = 0;
    }
}

// ---------------- 2: conv1(+inline bn1 fold) for blocks<NN; CSR scatter on the rest --
__global__ void __launch_bounds__(128) k_conv1sc(const float* __restrict__ x,
                                                const float* __restrict__ w,
                                                const float* __restrict__ g1,
                                                const float* __restrict__ b1,
                                                const float* __restrict__ m1,
                                                const float* __restrict__ v1,
                                                const int* __restrict__ edge) {
    int blk = blockIdx.x, tid = threadIdx.x;
    if (blk >= NN) {
        for (int e = (blk - NN)*128 + tid; e < EE; e += 32*128) {
            int dd = edge[EE + e];
            int pos = atomicAdd(&d_cursor[dd], 1);
            d_csrsrc[pos] = edge[e];
        }
        return;
    }
    __shared__ float xs[TT + 6];
    __shared__ float ws[7*C0];
    __shared__ float ss[C0], bs[C0];
    int n = blk;
    if (tid < TT) xs[tid + 3] = x[n*TT + tid];
    if (tid < 3)  { xs[tid] = 0.f; xs[TT + 3 + tid] = 0.f; }
    for (int i = tid; i < 7*C0; i += 128) ws[i] = w[i];
    if (tid < C0) {
        float s = g1[tid]*rsqrtf(v1[tid]+EPSB);
        ss[tid] = s; bs[tid] = b1[tid] - m1[tid]*s;
    }
    __syncthreads();
    int t = tid >> 1, cb = (tid & 1) * 16;
    float acc[16];
    #pragma unroll
    for (int c = 0; c < 16; c++) acc[c] = 0.f;
    #pragma unroll
    for (int k = 0; k < 7; k++) {
        float xv = xs[t + k];
        #pragma unroll
        for (int c = 0; c < 16; c++) acc[c] += xv * ws[k*C0 + cb + c];
    }
    uint4 o[2];
    __nv_bfloat162* ob = (__nv_bfloat162*)o;
    #pragma unroll
    for (int j = 0; j < 8; j++) {
        float f0 = fmaxf(acc[2*j]   * ss[cb+2*j]   + bs[cb+2*j],   0.f);
        float f1 = fmaxf(acc[2*j+1] * ss[cb+2*j+1] + bs[cb+2*j+1], 0.f);
        ob[j] = __floats2bfloat162_rn(f0, f1);
    }
    __nv_bfloat16* dst = &d_h1b[(n*TT + t)*C0 + cb];
    *(uint4*)dst = o[0];
    *(uint4*)(dst + 8) = o[1];
}

// ---------------- helpers ----------------
__device__ __forceinline__ void acc_u4(float* a, uint4 v, float w) {
    const __nv_bfloat162* b = (const __nv_bfloat162*)&v;
    #pragma unroll
    for (int j = 0; j < 4; j++) {
        float2 f = __bfloat1622float2(b[j]);
        a[2*j]   += w * f.x;
        a[2*j+1] += w * f.y;
    }
}
__device__ __forceinline__ void store_row8(__nv_bfloat16* p, const float* a, float sc) {
    uint4 o;
    __nv_bfloat162* b = (__nv_bfloat162*)&o;
    #pragma unroll
    for (int j = 0; j < 4; j++) b[j] = __floats2bfloat162_rn(a[2*j]*sc, a[2*j+1]*sc);
    *(uint4*)p = o;
}

// ---------------- bf16 mma macro ----------------
#define MMA_BF16(acc, A0, A1, A2, A3, B0, B1)                                   \
    asm volatile(                                                               \
        "mma.sync.aligned.m16n8k16.row.col.f32.bf16.bf16.f32 "                  \
        "{%0,%1,%2,%3}, {%4,%5,%6,%7}, {%8,%9}, {%0,%1,%2,%3};"                 \
        : "+f"(acc[0]), "+f"(acc[1]), "+f"(acc[2]), "+f"(acc[3])                \
        : "r"(A0), "r"(A1), "r"(A2), "r"(A3), "r"(B0), "r"(B1))

// Coalesced epilogue (stride 136 staging, conflict-free; 16B coalesced stores)
#define EPILOGUE_STORE(S_, acc_, NTN, dst_, rowbase_)                            \
    for (int half = 0; half < 2; half++) {                                       \
        __syncthreads();                                                         \
        if ((wid >> 2) == half) {                                                \
            int lr = (mrow & 63) + g;                                            \
            _Pragma("unroll")                                                    \
            for (int nt = 0; nt < NTN; nt++) {                                   \
                int c = nt*8 + 2*tg;                                             \
                *(__nv_bfloat162*)&S_[lr*136 + c] =                              \
                    __floats2bfloat162_rn(fmaxf(acc_[nt][0], 0.f),               \
                                          fmaxf(acc_[nt][1], 0.f));              \
                *(__nv_bfloat162*)&S_[(lr+8)*136 + c] =                          \
                    __floats2bfloat162_rn(fmaxf(acc_[nt][2], 0.f),               \
                                          fmaxf(acc_[nt][3], 0.f));              \
            }                                                                    \
        }                                                                        \
        __syncthreads();                                                         \
        _Pragma("unroll")                                                        \
        for (int i = tid; i < 1024; i += 256) {                                  \
            int r = i >> 4, c8 = (i & 15) * 8;                                   \
            *(uint4*)&dst_[(size_t)(rowbase_ + half*64 + r)*EMB + c8] =          \
                *(const uint4*)&S_[r*136 + c8];                                  \
        }                                                                        \
    }

// ---------------- 3: FUSED agg1+gcn1 (k_mmA): gather h1 -> As, mma, coalesced out ----
// Block: 2 nodes (128 rows x 32 k). Gather: thr 0-127 node0, 128-255 node1; 16 elem/thr.
__global__ void __launch_bounds__(256, 2) k_mmA(const float* __restrict__ bias) {
    __shared__ __nv_bfloat16 S[10240];   // As[0:5120) | Bs[5120:10240); epilogue reuses
    __nv_bfloat16* As = S;
    __nv_bfloat16* Bs = S + 5120;
    int tid = threadIdx.x;
    int n0 = blockIdx.x * 2;

    {   // ---- gather-aggregate phase ----
        int nl = tid >> 7, slot = tid & 127;
        int tt = slot >> 1, ch0 = (slot & 1) * 16;
        int node = n0 + nl;
        float di = d_dinv[node];
        const __nv_bfloat16* sp = &d_h1b[((size_t)node*TT + tt)*C0 + ch0];
        float a[16];
        {
            uint4 v0 = *(const uint4*)sp, v1 = *(const uint4*)(sp + 8);
            #pragma unroll
            for (int j = 0; j < 16; j++) a[j] = 0.f;
            acc_u4(a, v0, di); acc_u4(a + 8, v1, di);
        }
        int e0 = d_rowstart[node], e1 = d_rowstart[node+1];
        uint4 p0, p1; float ds = 0.f;
        if (e0 < e1) {
            int s = d_csrsrc[e0]; ds = d_dinv[s];
            const __nv_bfloat16* np = &d_h1b[((size_t)s*TT + tt)*C0 + ch0];
            p0 = *(const uint4*)np; p1 = *(const uint4*)(np + 8);
        }
        for (int e = e0; e < e1; e++) {
            uint4 c0 = p0, c1 = p1; float w = ds;
            if (e + 1 < e1) {
                int s = d_csrsrc[e+1]; ds = d_dinv[s];
                const __nv_bfloat16* np = &d_h1b[((size_t)s*TT + tt)*C0 + ch0];
                p0 = *(const uint4*)np; p1 = *(const uint4*)(np + 8);
            }
            acc_u4(a, c0, w); acc_u4(a + 8, c1, w);
        }
        __nv_bfloat162* dst = (__nv_bfloat162*)&As[(nl*64 + tt)*40 + ch0];
        #pragma unroll
        for (int j = 0; j < 8; j++) dst[j] = __floats2bfloat162_rn(a[2*j]*di, a[2*j+1]*di);
    }
    // ---- stage B ----
    #pragma unroll
    for (int i = tid; i < 512; i += 256) {
        int r = i >> 2, k8 = (i & 3) * 8;
        *(uint4*)&Bs[r*40 + k8] = *(const uint4*)&d_w1tb[r*C0 + k8];
    }
    __syncthreads();
    // ---- mma phase ----
    int wid = tid >> 5, lane = tid & 31;
    int g = lane >> 2, tg = lane & 3;
    int mrow = wid * 16;
    int rowbase = n0 * TT;
    float acc[16][4];
    #pragma unroll
    for (int nt = 0; nt < 16; nt++) {
        int c = nt*8 + 2*tg;
        float b0 = bias[c], b1 = bias[c+1];
        acc[nt][0] = b0; acc[nt][1] = b1; acc[nt][2] = b0; acc[nt][3] = b1;
    }
    #pragma unroll
    for (int ks = 0; ks < 32; ks += 16) {
        uint32_t a0 = *(const uint32_t*)&As[(mrow+g  )*40 + ks + 2*tg];
        uint32_t a1 = *(const uint32_t*)&As[(mrow+g+8)*40 + ks + 2*tg];
        uint32_t a2 = *(const uint32_t*)&As[(mrow+g  )*40 + ks + 2*tg + 8];
        uint32_t a3 = *(const uint32_t*)&As[(mrow+g+8)*40 + ks + 2*tg + 8];
        #pragma unroll
        for (int nt = 0; nt < 16; nt++) {
            uint32_t b0 = *(const uint32_t*)&Bs[(nt*8+g)*40 + ks + 2*tg];
            uint32_t b1 = *(const uint32_t*)&Bs[(nt*8+g)*40 + ks + 2*tg + 8];
            MMA_BF16(acc[nt], a0, a1, a2, a3, b0, b1);
        }
    }
    EPILOGUE_STORE(S, acc, 16, d_h2b, rowbase)
}

// ---------------- 4: agg2 (bf16), grid.y=4, 4-edge ILP gather ----------------
__global__ void __launch_bounds__(256) k_agg2b() {
    int node = blockIdx.x;
    int off  = blockIdx.y*2048 + threadIdx.x * 8;
    float di = d_dinv[node];
    float a[8] = {0,0,0,0,0,0,0,0};
    {
        uint4 v = *(const uint4*)(d_h2b + (size_t)node*8192 + off);
        acc_u4(a, v, di);
    }
    int e0 = d_rowstart[node], e1 = d_rowstart[node+1];
    int e = e0;
    for (; e + 4 <= e1; e += 4) {
        int s0 = d_csrsrc[e], s1 = d_csrsrc[e+1], s2 = d_csrsrc[e+2], s3 = d_csrsrc[e+3];
        float w0 = d_dinv[s0], w1 = d_dinv[s1], w2 = d_dinv[s2], w3 = d_dinv[s3];
        uint4 v0 = *(const uint4*)(d_h2b + (size_t)s0*8192 + off);
        uint4 v1 = *(const uint4*)(d_h2b + (size_t)s1*8192 + off);
        uint4 v2 = *(const uint4*)(d_h2b + (size_t)s2*8192 + off);
        uint4 v3 = *(const uint4*)(d_h2b + (size_t)s3*8192 + off);
        acc_u4(a, v0, w0); acc_u4(a, v1, w1); acc_u4(a, v2, w2); acc_u4(a, v3, w3);
    }
    for (; e < e1; e++) {
        int s = d_csrsrc[e];
        float w = d_dinv[s];
        uint4 v = *(const uint4*)(d_h2b + (size_t)s*8192 + off);
        acc_u4(a, v, w);
    }
    store_row8(d_a2b + (size_t)node*8192 + off, a, di);
}

// ---------------- 5: gcn2 matmul bf16 mma, coalesced epilogue -------------------------
__global__ void __launch_bounds__(256, 3) k_mm2b(const float* __restrict__ bias) {
    __shared__ __nv_bfloat16 S[10240];
    __nv_bfloat16* As = S;
    __nv_bfloat16* Bs = S + 5120;
    int tid = threadIdx.x;
    int wid = tid >> 5, lane = tid & 31;
    int g = lane >> 2, tg = lane & 3;
    int rowbase = blockIdx.x * 128;
    int mrow = wid * 16;

    float acc[16][4];
    #pragma unroll
    for (int nt = 0; nt < 16; nt++) {
        int c = nt*8 + 2*tg;
        float b0 = bias[c], b1 = bias[c+1];
        acc[nt][0] = b0; acc[nt][1] = b1; acc[nt][2] = b0; acc[nt][3] = b1;
    }
    for (int kc = 0; kc < 4; kc++) {
        #pragma unroll
        for (int i = tid; i < 512; i += 256) {
            int r = i >> 2, k8 = (i & 3) * 8;
            *(uint4*)&As[r*40 + k8] =
                *(const uint4*)&d_a2b[(size_t)(rowbase + r)*EMB + kc*32 + k8];
        }
        #pragma unroll
        for (int i = tid; i < 512; i += 256) {
            int r = i >> 2, k8 = (i & 3) * 8;
            *(uint4*)&Bs[r*40 + k8] = *(const uint4*)&d_w2tb[r*EMB + kc*32 + k8];
        }
        __syncthreads();
        #pragma unroll
        for (int ks = 0; ks < 32; ks += 16) {
            uint32_t a0 = *(const uint32_t*)&As[(mrow+g  )*40 + ks + 2*tg];
            uint32_t a1 = *(const uint32_t*)&As[(mrow+g+8)*40 + ks + 2*tg];
            uint32_t a2 = *(const uint32_t*)&As[(mrow+g  )*40 + ks + 2*tg + 8];
            uint32_t a3 = *(const uint32_t*)&As[(mrow+g+8)*40 + ks + 2*tg + 8];
            #pragma unroll
            for (int nt = 0; nt < 16; nt++) {
                uint32_t b0 = *(const uint32_t*)&Bs[(nt*8+g)*40 + ks + 2*tg];
                uint32_t b1 = *(const uint32_t*)&Bs[(nt*8+g)*40 + ks + 2*tg + 8];
                MMA_BF16(acc[nt], a0, a1, a2, a3, b0, b1);
            }
        }
        __syncthreads();
    }
    EPILOGUE_STORE(S, acc, 16, d_h2b, rowbase)
}

// ---------------- 6: conv2+bn2+pool+relu GEMM, fused graph-pool epilogue --------------
__global__ void __launch_bounds__(256, 2) k_conv2b(const int* __restrict__ batch) {
    __shared__ __nv_bfloat16 As[128*72];   // 18KB
    __shared__ __nv_bfloat16 Bs[64*72];    // 9KB
    int tid = threadIdx.x;
    int wid = tid >> 5, lane = tid & 31;
    int g = lane >> 2, tg = lane & 3;
    int n0 = blockIdx.x * 8;
    int mrow = wid * 16;

    float acc[8][4];
    #pragma unroll
    for (int nt = 0; nt < 8; nt++) {
        int c = nt*8 + 2*tg;
        float b0 = d_beff2[c], b1 = d_beff2[c+1];
        acc[nt][0] = b0; acc[nt][1] = b1; acc[nt][2] = b0; acc[nt][3] = b1;
    }
    for (int u = 0; u < 10; u++) {
        for (int h = 0; h < 2; h++) {
            #pragma unroll
            for (int i = tid; i < 1024; i += 256) {
                int r = i >> 3, k8 = (i & 7) * 8;
                uint4 v = make_uint4(0u, 0u, 0u, 0u);
                if (r < 112) {
                    int nl = r / 14, p = r - nl*14;
                    v = *(const uint4*)
                        &d_h2b[(size_t)((n0+nl)*TT + 4*p + u)*EMB + h*64 + k8];
                }
                *(uint4*)&As[r*72 + k8] = v;
            }
            #pragma unroll
            for (int i = tid; i < 512; i += 256) {
                int c = i >> 3, k8 = (i & 7) * 8;
                *(uint4*)&Bs[c*72 + k8] =
                    *(const uint4*)&d_weff2tb[(size_t)c*1280 + u*128 + h*64 + k8];
            }
            __syncthreads();
            #pragma unroll
            for (int ks = 0; ks < 64; ks += 16) {
                uint32_t a0 = *(const uint32_t*)&As[(mrow+g  )*72 + ks + 2*tg];
                uint32_t a1 = *(const uint32_t*)&As[(mrow+g+8)*72 + ks + 2*tg];
                uint32_t a2 = *(const uint32_t*)&As[(mrow+g  )*72 + ks + 2*tg + 8];
                uint32_t a3 = *(const uint32_t*)&As[(mrow+g+8)*72 + ks + 2*tg + 8];
                #pragma unroll
                for (int nt = 0; nt < 8; nt++) {
                    uint32_t b0 = *(const uint32_t*)&Bs[(nt*8+g)*72 + ks + 2*tg];
                    uint32_t b1 = *(const uint32_t*)&Bs[(nt*8+g)*72 + ks + 2*tg + 8];
                    MMA_BF16(acc[nt], a0, a1, a2, a3, b0, b1);
                }
            }
            __syncthreads();
        }
    }
    int r0 = mrow + g;
    if (r0 < 112) {
        int nl0 = r0 / 14, p0 = r0 - nl0*14;
        int base0 = batch[n0 + nl0]*(14*C1) + p0*C1;
        int r1 = r0 + 8;
        int nl1 = r1 / 14, p1 = r1 - nl1*14;
        int base1 = batch[n0 + nl1]*(14*C1) + p1*C1;
        #pragma unroll
        for (int nt = 0; nt < 8; nt++) {
            int c = nt*8 + 2*tg;
            atomicAdd(&d_gp[base0 + c],     fmaxf(acc[nt][0], 0.f));
            atomicAdd(&d_gp[base0 + c + 1], fmaxf(acc[nt][1], 0.f));
            atomicAdd(&d_gp[base1 + c],     fmaxf(acc[nt][2], 0.f));
            atomicAdd(&d_gp[base1 + c + 1], fmaxf(acc[nt][3], 0.f));
        }
    }
}

// ---------------- 7: conv3+bn3+pool+relu + dense + log_softmax (+restore d_gp zero) ---
__global__ void __launch_bounds__(128) k_final(const int* __restrict__ batch,
                                               const float* __restrict__ dw,
                                               const float* __restrict__ db,
                                               float* __restrict__ out) {
    __shared__ float gin[14*C1];
    __shared__ float flat[128];
    __shared__ float lg[4];
    __shared__ int scount;
    int b = blockIdx.x, tid = threadIdx.x;
    if (tid == 0) scount = 0;
    __syncthreads();
    int cnt = 0;
    for (int i = tid; i < NN; i += 128) cnt += (batch[i] == b);
    #pragma unroll
    for (int s = 16; s > 0; s >>= 1) cnt += __shfl_down_sync(0xffffffffu, cnt, s);
    if ((tid & 31) == 0) atomicAdd(&scount, cnt);
    for (int i = tid; i < 14*C1; i += 128) gin[i] = d_gp[b*14*C1 + i];
    __syncthreads();
    float inv = 1.f / (float)scount;
    for (int i = tid; i < 14*C1; i += 128) d_gp[b*14*C1 + i] = 0.f;
    int p = tid >> 6, c = tid & 63;
    float acc = d_beff3[c];
    for (int u = 0; u < 10; u++)
        for (int ci = 0; ci < C2; ci++)
            acc += gin[(4*p + u)*C2 + ci] * inv * d_weff3[(u*C2 + ci)*C2 + c];
    flat[p*64 + c] = fmaxf(acc, 0.f);
    __syncthreads();
    if (tid < 4) {
        float a = db[tid];
        for (int i = 0; i < 128; i++) a += flat[i] * dw[i*4 + tid];
        lg[tid] = a;
    }
    __syncthreads();
    if (tid == 0) {
        float m = fmaxf(fmaxf(lg[0], lg[1]), fmaxf(lg[2], lg[3]));
        float se = expf(lg[0]-m) + expf(lg[1]-m) + expf(lg[2]-m) + expf(lg[3]-m);
        float lse = logf(se) + m;
        for (int j = 0; j < 4; j++) out[b*4 + j] = lg[j] - lse;
    }
}

// ---------------- launcher ----------------
extern "C" void kernel_launch(void* const* d_in, const int* in_sizes, int n_in,
                              void* d_out, int out_size) {
    const float* x       = (const float*)d_in[0];
    const int*   edge    = (const int*)d_in[1];
    const int*   batch   = (const int*)d_in[2];
    const float* conv1_w = (const float*)d_in[3];
    const float* bn1_g   = (const float*)d_in[4];
    const float* bn1_b   = (const float*)d_in[5];
    const float* bn1_m   = (const float*)d_in[6];
    const float* bn1_v   = (const float*)d_in[7];
    const float* gcn1_w  = (const float*)d_in[8];
    const float* gcn1_b  = (const float*)d_in[9];
    const float* gcn2_w  = (const float*)d_in[10];
    const float* gcn2_b  = (const float*)d_in[11];
    const float* conv2_w = (const float*)d_in[12];
    const float* bn2_g   = (const float*)d_in[13];
    const float* bn2_b   = (const float*)d_in[14];
    const float* bn2_m   = (const float*)d_in[15];
    const float* bn2_v   = (const float*)d_in[16];
    const float* conv3_w = (const float*)d_in[17];
    const float* bn3_g   = (const float*)d_in[18];
    const float* bn3_b   = (const float*)d_in[19];
    const float* bn3_m   = (const float*)d_in[20];
    const float* bn3_v   = (const float*)d_in[21];
    const float* dense_w = (const float*)d_in[22];
    const float* dense_b = (const float*)d_in[23];
    float* out = (float*)d_out;

    k_prep<<<320, 256>>>(edge, gcn1_w, gcn2_w,
                         conv2_w, bn2_g, bn2_b, bn2_m, bn2_v,
                         conv3_w, bn3_g, bn3_b, bn3_m, bn3_v);
    k_conv1sc<<<NN + 32, 128>>>(x, conv1_w, bn1_g, bn1_b, bn1_m, bn1_v, edge);
    k_mmA<<<1024, 256>>>(gcn1_b);
    k_agg2b<<<dim3(NN, 4), 256>>>();
    k_mm2b<<<1024, 256>>>(gcn2_b);
    k_conv2b<<<256, 256>>>(batch);
    k_final<<<BB, 128>>>(batch, dense_w, dense_b, out);
}

// round 14
// speedup vs baseline: 1.0342x; 1.0030x over previous
#include <cuda_runtime.h>
#include <cuda_bf16.h>
#include <math.h>
#include <stdint.h>

#define NN  2048
#define TT  64
#define EE  16384
#define BB  64
#define C0  32
#define EMB 128
#define C1  64
#define C2  64
#define EPSB 1e-5f

// ---------------- scratch (device globals; BSS -> zero at load) ----------------
__device__ __nv_bfloat16 d_h1b[NN*TT*C0];    // conv1 out (8MB)
__device__ __nv_bfloat16 d_h2b[NN*TT*EMB];   // gcn1/gcn2 out (32MB)
__device__ __nv_bfloat16 d_a2b[NN*TT*EMB];   // agg2 out  (32MB)
__device__ float d_gp[BB*14*C1];             // INVARIANT: zero at entry (k_final re-zeros)
__device__ int   d_rowcnt[NN];               // INVARIANT: zero at entry (prep last block re-zeros)
__device__ unsigned d_done;                  // INVARIANT: zero at entry (prep last block re-zeros)
__device__ int   d_rowstart[NN+1];
__device__ int   d_cursor[NN];
__device__ int   d_csrsrc[EE];
__device__ float d_dinv[NN];
__device__ __nv_bfloat16 d_w1tb[EMB*C0];       // gcn1 W transposed [n][k] bf16
__device__ __nv_bfloat16 d_w2tb[EMB*EMB];      // gcn2 W transposed [n][k] bf16
__device__ __nv_bfloat16 d_weff2tb[C1*1280];   // conv2 eff W transposed [c][u*128+ci] bf16
__device__ float d_beff2[C1];
__device__ float d_weff3[10*C2*C2];
__device__ float d_beff3[C2];

// ---------------- 1: prep (weight folds + degree count) + LAST-BLOCK scan ------------
__global__ void __launch_bounds__(256) k_prep(const int* __restrict__ edge,
                       const float* __restrict__ w1, const float* __restrict__ wg2,
                       const float* __restrict__ w2, const float* __restrict__ g2,
                       const float* __restrict__ b2, const float* __restrict__ m2,
                       const float* __restrict__ v2,
                       const float* __restrict__ w3, const float* __restrict__ g3,
                       const float* __restrict__ b3, const float* __restrict__ m3,
                       const float* __restrict__ v3) {
    __shared__ int sc[NN];
    __shared__ int st[256];
    __shared__ bool s_last;
    int tid = threadIdx.x;
    int i = blockIdx.x * blockDim.x + tid;
    if (i < EE) atomicAdd(&d_rowcnt[edge[EE + i]], 1);
    if (i < C1) { float s = g2[i]*rsqrtf(v2[i]+EPSB); d_beff2[i]=b2[i]-m2[i]*s; }
    if (i < C2) { float s = g3[i]*rsqrtf(v3[i]+EPSB); d_beff3[i]=b3[i]-m3[i]*s; }
    if (i < EMB*C0) {
        int n = i >> 5, k = i & 31;
        d_w1tb[i] = __float2bfloat16(w1[k*EMB + n]);
    }
    if (i < EMB*EMB) {
        int n = i >> 7, k = i & 127;
        d_w2tb[i] = __float2bfloat16(wg2[k*EMB + n]);
    }
    if (i < C1*1280) {
        int c = i / 1280, kk = i - c*1280;
        int u = kk >> 7, ci = kk & 127;
        float s = g2[c]*rsqrtf(v2[c]+EPSB);
        int klo = u-3; if (klo < 0) klo = 0;
        int khi = u < 6 ? u : 6;
        float acc = 0.f;
        for (int k = klo; k <= khi; k++) acc += w2[(k*EMB+ci)*C1 + c];
        d_weff2tb[i] = __float2bfloat16(acc * s * 0.25f);
    }
    if (i < 10*C2*C2) {
        int c = i % C2; int ci = (i / C2) % C2; int u = i / (C2*C2);
        float s = g3[c]*rsqrtf(v3[c]+EPSB);
        int klo = u-3; if (klo < 0) klo = 0;
        int khi = u < 6 ? u : 6;
        float acc = 0.f;
        for (int k = klo; k <= khi; k++) acc += w3[(k*C2+ci)*C2 + c];
        d_weff3[i] = acc * s * 0.25f;
    }
    __syncthreads();
    if (tid == 0) {
        __threadfence();
        unsigned t = atomicAdd(&d_done, 1u);
        s_last = (t == gridDim.x - 1);
    }
    __syncthreads();
    if (!s_last) return;

    int base = tid * 8;
    int run = 0;
    #pragma unroll
    for (int j = 0; j < 8; j++) {
        int c = d_rowcnt[base + j];
        d_rowcnt[base + j] = 0;
        d_dinv[base + j] = rsqrtf((float)(c + 1));
        run += c;
        sc[base + j] = run;
    }
    st[tid] = run;
    __syncthreads();
    for (int off = 1; off < 256; off <<= 1) {
        int v = (tid >= off) ? st[tid - off] : 0;
        __syncthreads();
        st[tid] += v;
        __syncthreads();
    }
    int chunk_excl = (tid == 0) ? 0 : st[tid - 1];
    #pragma unroll
    for (int j = 0; j < 8; j++) {
        int excl = chunk_excl + ((j == 0) ? 0 : sc[base + j - 1]);
        d_rowstart[base + j] = excl;
        d_cursor[base + j]   = excl;
    }
    if (tid == 255) {
        d_rowstart[NN] = chunk_excl + sc[base + 7];
        d_done = 0;
    }
}

// ---------------- 2: conv1(+inline bn1 fold) for blocks<NN; CSR scatter on the rest --
__global__ void __launch_bounds__(128) k_conv1sc(const float* __restrict__ x,
                                                const float* __restrict__ w,
                                                const float* __restrict__ g1,
                                                const float* __restrict__ b1,
                                                const float* __restrict__ m1,
                                                const float* __restrict__ v1,
                                                const int* __restrict__ edge) {
    int blk = blockIdx.x, tid = threadIdx.x;
    if (blk >= NN) {
        for (int e = (blk - NN)*128 + tid; e < EE; e += 32*128) {
            int dd = edge[EE + e];
            int pos = atomicAdd(&d_cursor[dd], 1);
            d_csrsrc[pos] = edge[e];
        }
        return;
    }
    __shared__ float xs[TT + 6];
    __shared__ float ws[7*C0];
    __shared__ float ss[C0], bs[C0];
    int n = blk;
    if (tid < TT) xs[tid + 3] = x[n*TT + tid];
    if (tid < 3)  { xs[tid] = 0.f; xs[TT + 3 + tid] = 0.f; }
    for (int i = tid; i < 7*C0; i += 128) ws[i] = w[i];
    if (tid < C0) {
        float s = g1[tid]*rsqrtf(v1[tid]+EPSB);
        ss[tid] = s; bs[tid] = b1[tid] - m1[tid]*s;
    }
    __syncthreads();
    int t = tid >> 1, cb = (tid & 1) * 16;
    float acc[16];
    #pragma unroll
    for (int c = 0; c < 16; c++) acc[c] = 0.f;
    #pragma unroll
    for (int k = 0; k < 7; k++) {
        float xv = xs[t + k];
        #pragma unroll
        for (int c = 0; c < 16; c++) acc[c] += xv * ws[k*C0 + cb + c];
    }
    uint4 o[2];
    __nv_bfloat162* ob = (__nv_bfloat162*)o;
    #pragma unroll
    for (int j = 0; j < 8; j++) {
        float f0 = fmaxf(acc[2*j]   * ss[cb+2*j]   + bs[cb+2*j],   0.f);
        float f1 = fmaxf(acc[2*j+1] * ss[cb+2*j+1] + bs[cb+2*j+1], 0.f);
        ob[j] = __floats2bfloat162_rn(f0, f1);
    }
    __nv_bfloat16* dst = &d_h1b[(n*TT + t)*C0 + cb];
    *(uint4*)dst = o[0];
    *(uint4*)(dst + 8) = o[1];
}

// ---------------- helpers ----------------
__device__ __forceinline__ void acc_u4(float* a, uint4 v, float w) {
    const __nv_bfloat162* b = (const __nv_bfloat162*)&v;
    #pragma unroll
    for (int j = 0; j < 4; j++) {
        float2 f = __bfloat1622float2(b[j]);
        a[2*j]   += w * f.x;
        a[2*j+1] += w * f.y;
    }
}
__device__ __forceinline__ void store_row8(__nv_bfloat16* p, const float* a, float sc) {
    uint4 o;
    __nv_bfloat162* b = (__nv_bfloat162*)&o;
    #pragma unroll
    for (int j = 0; j < 4; j++) b[j] = __floats2bfloat162_rn(a[2*j]*sc, a[2*j+1]*sc);
    *(uint4*)p = o;
}
__device__ __forceinline__ uint32_t smem_u32(const void* p) {
    return (uint32_t)__cvta_generic_to_shared(p);
}

// ---------------- mma / ldmatrix macros ----------------
#define MMA_BF16(acc, A0, A1, A2, A3, B0, B1)                                   \
    asm volatile(                                                               \
        "mma.sync.aligned.m16n8k16.row.col.f32.bf16.bf16.f32 "                  \
        "{%0,%1,%2,%3}, {%4,%5,%6,%7}, {%8,%9}, {%0,%1,%2,%3};"                 \
        : "+f"(acc[0]), "+f"(acc[1]), "+f"(acc[2]), "+f"(acc[3])                \
        : "r"(A0), "r"(A1), "r"(A2), "r"(A3), "r"(B0), "r"(B1))

#define LDSM_X4(R0, R1, R2, R3, ADDR)                                           \
    asm volatile("ldmatrix.sync.aligned.m8n8.x4.shared.b16 {%0,%1,%2,%3}, [%4];"\
        : "=r"(R0), "=r"(R1), "=r"(R2), "=r"(R3) : "r"(ADDR))

// Coalesced epilogue (stride 136 staging, conflict-free; 16B coalesced stores)
#define EPILOGUE_STORE(S_, acc_, NTN, dst_, rowbase_)                            \
    for (int half = 0; half < 2; half++) {                                       \
        __syncthreads();                                                         \
        if ((wid >> 2) == half) {                                                \
            int lr = (mrow & 63) + g;                                            \
            _Pragma("unroll")                                                    \
            for (int nt = 0; nt < NTN; nt++) {                                   \
                int c = nt*8 + 2*tg;                                             \
                *(__nv_bfloat162*)&S_[lr*136 + c] =                              \
                    __floats2bfloat162_rn(fmaxf(acc_[nt][0], 0.f),               \
                                          fmaxf(acc_[nt][1], 0.f));              \
                *(__nv_bfloat162*)&S_[(lr+8)*136 + c] =                          \
                    __floats2bfloat162_rn(fmaxf(acc_[nt][2], 0.f),               \
                                          fmaxf(acc_[nt][3], 0.f));              \
            }                                                                    \
        }                                                                        \
        __syncthreads();                                                         \
        _Pragma("unroll")                                                        \
        for (int i = tid; i < 1024; i += 256) {                                  \
            int r = i >> 4, c8 = (i & 15) * 8;                                   \
            *(uint4*)&dst_[(size_t)(rowbase_ + half*64 + r)*EMB + c8] =          \
                *(const uint4*)&S_[r*136 + c8];                                  \
        }                                                                        \
    }

// ---------------- 3: FUSED agg1+gcn1 (k_mmA): gather h1 -> As, ldmatrix mma ----------
__global__ void __launch_bounds__(256, 2) k_mmA(const float* __restrict__ bias) {
    __shared__ __nv_bfloat16 S[10240];   // As[0:5120) | Bs[5120:10240); epilogue reuses
    __nv_bfloat16* As = S;
    __nv_bfloat16* Bs = S + 5120;
    int tid = threadIdx.x;
    int n0 = blockIdx.x * 2;

    {   // ---- gather-aggregate phase ----
        int nl = tid >> 7, slot = tid & 127;
        int tt = slot >> 1, ch0 = (slot & 1) * 16;
        int node = n0 + nl;
        float di = d_dinv[node];
        const __nv_bfloat16* sp = &d_h1b[((size_t)node*TT + tt)*C0 + ch0];
        float a[16];
        {
            uint4 v0 = *(const uint4*)sp, v1 = *(const uint4*)(sp + 8);
            #pragma unroll
            for (int j = 0; j < 16; j++) a[j] = 0.f;
            acc_u4(a, v0, di); acc_u4(a + 8, v1, di);
        }
        int e0 = d_rowstart[node], e1 = d_rowstart[node+1];
        uint4 p0, p1; float ds = 0.f;
        if (e0 < e1) {
            int s = d_csrsrc[e0]; ds = d_dinv[s];
            const __nv_bfloat16* np = &d_h1b[((size_t)s*TT + tt)*C0 + ch0];
            p0 = *(const uint4*)np; p1 = *(const uint4*)(np + 8);
        }
        for (int e = e0; e < e1; e++) {
            uint4 c0 = p0, c1 = p1; float w = ds;
            if (e + 1 < e1) {
                int s = d_csrsrc[e+1]; ds = d_dinv[s];
                const __nv_bfloat16* np = &d_h1b[((size_t)s*TT + tt)*C0 + ch0];
                p0 = *(const uint4*)np; p1 = *(const uint4*)(np + 8);
            }
            acc_u4(a, c0, w); acc_u4(a + 8, c1, w);
        }
        __nv_bfloat162* dst = (__nv_bfloat162*)&As[(nl*64 + tt)*40 + ch0];
        #pragma unroll
        for (int j = 0; j < 8; j++) dst[j] = __floats2bfloat162_rn(a[2*j]*di, a[2*j+1]*di);
    }
    // ---- stage B ----
    #pragma unroll
    for (int i = tid; i < 512; i += 256) {
        int r = i >> 2, k8 = (i & 3) * 8;
        *(uint4*)&Bs[r*40 + k8] = *(const uint4*)&d_w1tb[r*C0 + k8];
    }
    __syncthreads();
    // ---- mma phase (ldmatrix fragments) ----
    int wid = tid >> 5, lane = tid & 31;
    int g = lane >> 2, tg = lane & 3;
    int mrow = wid * 16;
    int rowbase = n0 * TT;
    int lt = lane >> 3, lr = lane & 7;
    float acc[16][4];
    #pragma unroll
    for (int nt = 0; nt < 16; nt++) {
        int c = nt*8 + 2*tg;
        float b0 = bias[c], b1 = bias[c+1];
        acc[nt][0] = b0; acc[nt][1] = b1; acc[nt][2] = b0; acc[nt][3] = b1;
    }
    #pragma unroll
    for (int ks = 0; ks < 32; ks += 16) {
        uint32_t a0, a1, a2, a3;
        LDSM_X4(a0, a1, a2, a3,
                smem_u32(&As[(mrow + (lt&1)*8 + lr)*40 + ks + (lt>>1)*8]));
        uint32_t bbase = smem_u32(&Bs[((lt>>1)*8 + lr)*40 + ks + (lt&1)*8]);
        #pragma unroll
        for (int nt = 0; nt < 16; nt += 2) {
            uint32_t b00, b01, b10, b11;
            LDSM_X4(b00, b01, b10, b11, bbase + nt*640);
            MMA_BF16(acc[nt],   a0, a1, a2, a3, b00, b01);
            MMA_BF16(acc[nt+1], a0, a1, a2, a3, b10, b11);
        }
    }
    EPILOGUE_STORE(S, acc, 16, d_h2b, rowbase)
}

// ---------------- 4: agg2 (bf16), grid.y=4, 4-edge ILP gather ----------------
__global__ void __launch_bounds__(256) k_agg2b() {
    int node = blockIdx.x;
    int off  = blockIdx.y*2048 + threadIdx.x * 8;
    float di = d_dinv[node];
    float a[8] = {0,0,0,0,0,0,0,0};
    {
        uint4 v = *(const uint4*)(d_h2b + (size_t)node*8192 + off);
        acc_u4(a, v, di);
    }
    int e0 = d_rowstart[node], e1 = d_rowstart[node+1];
    int e = e0;
    for (; e + 4 <= e1; e += 4) {
        int s0 = d_csrsrc[e], s1 = d_csrsrc[e+1], s2 = d_csrsrc[e+2], s3 = d_csrsrc[e+3];
        float w0 = d_dinv[s0], w1 = d_dinv[s1], w2 = d_dinv[s2], w3 = d_dinv[s3];
        uint4 v0 = *(const uint4*)(d_h2b + (size_t)s0*8192 + off);
        uint4 v1 = *(const uint4*)(d_h2b + (size_t)s1*8192 + off);
        uint4 v2 = *(const uint4*)(d_h2b + (size_t)s2*8192 + off);
        uint4 v3 = *(const uint4*)(d_h2b + (size_t)s3*8192 + off);
        acc_u4(a, v0, w0); acc_u4(a, v1, w1); acc_u4(a, v2, w2); acc_u4(a, v3, w3);
    }
    for (; e < e1; e++) {
        int s = d_csrsrc[e];
        float w = d_dinv[s];
        uint4 v = *(const uint4*)(d_h2b + (size_t)s*8192 + off);
        acc_u4(a, v, w);
    }
    store_row8(d_a2b + (size_t)node*8192 + off, a, di);
}

// ---------------- 5: gcn2 matmul bf16 mma, ldmatrix frags, coalesced epilogue ---------
__global__ void __launch_bounds__(256, 3) k_mm2b(const float* __restrict__ bias) {
    __shared__ __nv_bfloat16 S[10240];
    __nv_bfloat16* As = S;
    __nv_bfloat16* Bs = S + 5120;
    int tid = threadIdx.x;
    int wid = tid >> 5, lane = tid & 31;
    int g = lane >> 2, tg = lane & 3;
    int rowbase = blockIdx.x * 128;
    int mrow = wid * 16;
    int lt = lane >> 3, lr = lane & 7;

    float acc[16][4];
    #pragma unroll
    for (int nt = 0; nt < 16; nt++) {
        int c = nt*8 + 2*tg;
        float b0 = bias[c], b1 = bias[c+1];
        acc[nt][0] = b0; acc[nt][1] = b1; acc[nt][2] = b0; acc[nt][3] = b1;
    }
    for (int kc = 0; kc < 4; kc++) {
        #pragma unroll
        for (int i = tid; i < 512; i += 256) {
            int r = i >> 2, k8 = (i & 3) * 8;
            *(uint4*)&As[r*40 + k8] =
                *(const uint4*)&d_a2b[(size_t)(rowbase + r)*EMB + kc*32 + k8];
        }
        #pragma unroll
        for (int i = tid; i < 512; i += 256) {
            int r = i >> 2, k8 = (i & 3) * 8;
            *(uint4*)&Bs[r*40 + k8] = *(const uint4*)&d_w2tb[r*EMB + kc*32 + k8];
        }
        __syncthreads();
        #pragma unroll
        for (int ks = 0; ks < 32; ks += 16) {
            uint32_t a0, a1, a2, a3;
            LDSM_X4(a0, a1, a2, a3,
                    smem_u32(&As[(mrow + (lt&1)*8 + lr)*40 + ks + (lt>>1)*8]));
            uint32_t bbase = smem_u32(&Bs[((lt>>1)*8 + lr)*40 + ks + (lt&1)*8]);
            #pragma unroll
            for (int nt = 0; nt < 16; nt += 2) {
                uint32_t b00, b01, b10, b11;
                LDSM_X4(b00, b01, b10, b11, bbase + nt*640);
                MMA_BF16(acc[nt],   a0, a1, a2, a3, b00, b01);
                MMA_BF16(acc[nt+1], a0, a1, a2, a3, b10, b11);
            }
        }
        __syncthreads();
    }
    EPILOGUE_STORE(S, acc, 16, d_h2b, rowbase)
}

// ---------------- 6: conv2+bn2+pool+relu GEMM, ldmatrix frags, graph-pool epilogue ----
__global__ void __launch_bounds__(256, 2) k_conv2b(const int* __restrict__ batch) {
    __shared__ __nv_bfloat16 As[128*72];   // 18KB
    __shared__ __nv_bfloat16 Bs[64*72];    // 9KB
    int tid = threadIdx.x;
    int wid = tid >> 5, lane = tid & 31;
    int g = lane >> 2, tg = lane & 3;
    int n0 = blockIdx.x * 8;
    int mrow = wid * 16;
    int lt = lane >> 3, lr = lane & 7;

    float acc[8][4];
    #pragma unroll
    for (int nt = 0; nt < 8; nt++) {
        int c = nt*8 + 2*tg;
        float b0 = d_beff2[c], b1 = d_beff2[c+1];
        acc[nt][0] = b0; acc[nt][1] = b1; acc[nt][2] = b0; acc[nt][3] = b1;
    }
    for (int u = 0; u < 10; u++) {
        for (int h = 0; h < 2; h++) {
            #pragma unroll
            for (int i = tid; i < 1024; i += 256) {
                int r = i >> 3, k8 = (i & 7) * 8;
                uint4 v = make_uint4(0u, 0u, 0u, 0u);
                if (r < 112) {
                    int nl = r / 14, p = r - nl*14;
                    v = *(const uint4*)
                        &d_h2b[(size_t)((n0+nl)*TT + 4*p + u)*EMB + h*64 + k8];
                }
                *(uint4*)&As[r*72 + k8] = v;
            }
            #pragma unroll
            for (int i = tid; i < 512; i += 256) {
                int c = i >> 3, k8 = (i & 7) * 8;
                *(uint4*)&Bs[c*72 + k8] =
                    *(const uint4*)&d_weff2tb[(size_t)c*1280 + u*128 + h*64 + k8];
            }
            __syncthreads();
            #pragma unroll
            for (int ks = 0; ks < 64; ks += 16) {
                uint32_t a0, a1, a2, a3;
                LDSM_X4(a0, a1, a2, a3,
                        smem_u32(&As[(mrow + (lt&1)*8 + lr)*72 + ks + (lt>>1)*8]));
                uint32_t bbase = smem_u32(&Bs[((lt>>1)*8 + lr)*72 + ks + (lt&1)*8]);
                #pragma unroll
                for (int nt = 0; nt < 8; nt += 2) {
                    uint32_t b00, b01, b10, b11;
                    LDSM_X4(b00, b01, b10, b11, bbase + nt*1152);
                    MMA_BF16(acc[nt],   a0, a1, a2, a3, b00, b01);
                    MMA_BF16(acc[nt+1], a0, a1, a2, a3, b10, b11);
                }
            }
            __syncthreads();
        }
    }
    int r0 = mrow + g;
    if (r0 < 112) {
        int nl0 = r0 / 14, p0 = r0 - nl0*14;
        int base0 = batch[n0 + nl0]*(14*C1) + p0*C1;
        int r1 = r0 + 8;
        int nl1 = r1 / 14, p1 = r1 - nl1*14;
        int base1 = batch[n0 + nl1]*(14*C1) + p1*C1;
        #pragma unroll
        for (int nt = 0; nt < 8; nt++) {
            int c = nt*8 + 2*tg;
            atomicAdd(&d_gp[base0 + c],     fmaxf(acc[nt][0], 0.f));
            atomicAdd(&d_gp[base0 + c + 1], fmaxf(acc[nt][1], 0.f));
            atomicAdd(&d_gp[base1 + c],     fmaxf(acc[nt][2], 0.f));
            atomicAdd(&d_gp[base1 + c + 1], fmaxf(acc[nt][3], 0.f));
        }
    }
}

// ---------------- 7: conv3+bn3+pool+relu + dense + log_softmax (+restore d_gp zero) ---
__global__ void __launch_bounds__(128) k_final(const int* __restrict__ batch,
                                               const float* __restrict__ dw,
                                               const float* __restrict__ db,
                                               float* __restrict__ out) {
    __shared__ float gin[14*C1];
    __shared__ float flat[128];
    __shared__ float lg[4];
    __shared__ int scount;
    int b = blockIdx.x, tid = threadIdx.x;
    if (tid == 0) scount = 0;
    __syncthreads();
    int cnt = 0;
    for (int i = tid; i < NN; i += 128) cnt += (batch[i] == b);
    #pragma unroll
    for (int s = 16; s > 0; s >>= 1) cnt += __shfl_down_sync(0xffffffffu, cnt, s);
    if ((tid & 31) == 0) atomicAdd(&scount, cnt);
    for (int i = tid; i < 14*C1; i += 128) gin[i] = d_gp[b*14*C1 + i];
    __syncthreads();
    float inv = 1.f / (float)scount;
    for (int i = tid; i < 14*C1; i += 128) d_gp[b*14*C1 + i] = 0.f;
    int p = tid >> 6, c = tid & 63;
    float acc = d_beff3[c];
    for (int u = 0; u < 10; u++)
        for (int ci = 0; ci < C2; ci++)
            acc += gin[(4*p + u)*C2 + ci] * inv * d_weff3[(u*C2 + ci)*C2 + c];
    flat[p*64 + c] = fmaxf(acc, 0.f);
    __syncthreads();
    if (tid < 4) {
        float a = db[tid];
        for (int i = 0; i < 128; i++) a += flat[i] * dw[i*4 + tid];
        lg[tid] = a;
    }
    __syncthreads();
    if (tid == 0) {
        float m = fmaxf(fmaxf(lg[0], lg[1]), fmaxf(lg[2], lg[3]));
        float se = expf(lg[0]-m) + expf(lg[1]-m) + expf(lg[2]-m) + expf(lg[3]-m);
        float lse = logf(se) + m;
        for (int j = 0; j < 4; j++) out[b*4 + j] = lg[j] - lse;
    }
}

// ---------------- launcher ----------------
extern "C" void kernel_launch(void* const* d_in, const int* in_sizes, int n_in,
                              void* d_out, int out_size) {
    const float* x       = (const float*)d_in[0];
    const int*   edge    = (const int*)d_in[1];
    const int*   batch   = (const int*)d_in[2];
    const float* conv1_w = (const float*)d_in[3];
    const float* bn1_g   = (const float*)d_in[4];
    const float* bn1_b   = (const float*)d_in[5];
    const float* bn1_m   = (const float*)d_in[6];
    const float* bn1_v   = (const float*)d_in[7];
    const float* gcn1_w  = (const float*)d_in[8];
    const float* gcn1_b  = (const float*)d_in[9];
    const float* gcn2_w  = (const float*)d_in[10];
    const float* gcn2_b  = (const float*)d_in[11];
    const float* conv2_w = (const float*)d_in[12];
    const float* bn2_g   = (const float*)d_in[13];
    const float* bn2_b   = (const float*)d_in[14];
    const float* bn2_m   = (const float*)d_in[15];
    const float* bn2_v   = (const float*)d_in[16];
    const float* conv3_w = (const float*)d_in[17];
    const float* bn3_g   = (const float*)d_in[18];
    const float* bn3_b   = (const float*)d_in[19];
    const float* bn3_m   = (const float*)d_in[20];
    const float* bn3_v   = (const float*)d_in[21];
    const float* dense_w = (const float*)d_in[22];
    const float* dense_b = (const float*)d_in[23];
    float* out = (float*)d_out;

    k_prep<<<320, 256>>>(edge, gcn1_w, gcn2_w,
                         conv2_w, bn2_g, bn2_b, bn2_m, bn2_v,
                         conv3_w, bn3_g, bn3_b, bn3_m, bn3_v);
    k_conv1sc<<<NN + 32, 128>>>(x, conv1_w, bn1_g, bn1_b, bn1_m, bn1_v, edge);
    k_mmA<<<1024, 256>>>(gcn1_b);
    k_agg2b<<<dim3(NN, 4), 256>>>();
    k_mm2b<<<1024, 256>>>(gcn2_b);
    k_conv2b<<<256, 256>>>(batch);
    k_final<<<BB, 128>>>(batch, dense_w, dense_b, out);
}